// round 9
// baseline (speedup 1.0000x reference)
#include <cuda_runtime.h>
#include <cuda_fp16.h>
#include <cuda_pipeline.h>
#include <math.h>
#include <stdint.h>

#define BSZ 64
#define SEQ 256
#define MROWS (BSZ*SEQ)   // 16384
#define INF 1024
#define UFD 512
#define OFD 512

#define TILE_B  10240     // 128 rows x 80B (32 fp16 + 8 pad)
#define STAGE_B 30720     // 3 tiles (Ah, Al, Bh)
#define NSTAGE  3
#define SMEM_GEMM (NSTAGE*STAGE_B)        // 92160
#define SMEM_ATT  (NSTAGE*STAGE_B + 1024) // + srow/scol

// ---------------- scratch (__device__ globals; no runtime alloc) ----------------
__device__ __align__(16) float g_D[MROWS*OFD];   // pre-gating linear d
__device__ __align__(16) __half g_Xdh[MROWS*INF];
__device__ __align__(16) __half g_Xdl[MROWS*INF];
__device__ __align__(16) __half g_Xuh[MROWS*UFD];
__device__ __align__(16) __half g_Xul[MROWS*UFD];
__device__ __align__(16) __half g_Wdh[OFD*INF];
__device__ __align__(16) __half g_Wuh[OFD*UFD];
__device__ __align__(16) __half g_Wth[OFD*OFD];   // W^T: Wt[e][d] = W[d][e]
__device__ __align__(16) __half g_Dh[MROWS*OFD];  // gated d, split
__device__ __align__(16) __half g_Dl[MROWS*OFD];
__device__ __align__(16) __half g_Uh[MROWS*OFD];  // gated u, split
__device__ __align__(16) __half g_Ul[MROWS*OFD];
__device__ __align__(16) __half g_Eh[MROWS*OFD];
__device__ __align__(16) __half g_El[MROWS*OFD];
__device__ float g_rowpart[BSZ*SEQ*2];
__device__ float g_colpart[BSZ*SEQ*2];

// ---------------- helpers ----------------
__device__ __forceinline__ uint32_t smem_to_u32(const void* p) {
    uint32_t a;
    asm("{ .reg .u64 t; cvta.to.shared.u64 t, %1; cvt.u32.u64 %0, t; }" : "=r"(a) : "l"(p));
    return a;
}
__device__ __forceinline__ void ldmx4(uint32_t r[4], uint32_t addr) {
    asm volatile("ldmatrix.sync.aligned.m8n8.x4.shared.b16 {%0,%1,%2,%3}, [%4];"
        : "=r"(r[0]), "=r"(r[1]), "=r"(r[2]), "=r"(r[3]) : "r"(addr));
}
__device__ __forceinline__ void mma16816(float c[4], const uint32_t a[4], const uint32_t b[2]) {
    asm volatile("mma.sync.aligned.m16n8k16.row.col.f32.f16.f16.f32 "
        "{%0,%1,%2,%3}, {%4,%5,%6,%7}, {%8,%9}, {%0,%1,%2,%3};"
        : "+f"(c[0]), "+f"(c[1]), "+f"(c[2]), "+f"(c[3])
        : "r"(a[0]), "r"(a[1]), "r"(a[2]), "r"(a[3]), "r"(b[0]), "r"(b[1]));
}
__device__ __forceinline__ float sigm(float x) { return 1.0f / (1.0f + __expf(-x)); }

__device__ __forceinline__ void pack2h(float v0, float v1, uint32_t& hi, uint32_t& lo) {
    __half h0 = __float2half_rn(v0), h1 = __float2half_rn(v1);
    __half2 hh; hh.x = h0; hh.y = h1;
    __half2 ll;
    ll.x = __float2half_rn(v0 - __half2float(h0));
    ll.y = __float2half_rn(v1 - __half2float(h1));
    hi = *reinterpret_cast<uint32_t*>(&hh);
    lo = *reinterpret_cast<uint32_t*>(&ll);
}

// ---------------- mma mainloop: acc[4][4][4] += (Ah+Al)(128xK) * Bh(128xK)^T --------
// Row-major, k contiguous. BM=BN=128, BK=32, 8 warps (2x4), warp tile 64x32.
// 3-stage cp.async pipeline, ONE __syncthreads per k-tile.
__device__ __forceinline__ void gemm2(
    const __half* __restrict__ Ah, const __half* __restrict__ Al, int lda,
    const __half* __restrict__ Bh, int ldb,
    int K, char* smem, float (&acc)[4][4][4])
{
    int tid = threadIdx.x;
    int lane = tid & 31, wid = tid >> 5;
    int wm = (wid & 1) * 64, wn = (wid >> 1) * 32;
    uint32_t sb = smem_to_u32(smem);

    auto fill = [&](int s, int kt) {
        int k0 = kt * 32;
        #pragma unroll
        for (int t = 0; t < 3; t++) {
            const __half* bp = (t == 0) ? Ah : (t == 1) ? Al : Bh;
            int ld = (t < 2) ? lda : ldb;
            #pragma unroll
            for (int h = 0; h < 2; h++) {
                int chunk = h * 256 + tid;          // 0..511 = 128 rows x 4 chunks
                int row = chunk >> 2, c4 = chunk & 3;
                __pipeline_memcpy_async(
                    smem + s * STAGE_B + t * TILE_B + row * 80 + c4 * 16,
                    bp + (size_t)row * ld + k0 + c4 * 8, 16);
            }
        }
        __pipeline_commit();
    };

    // per-lane ldmatrix address components
    uint32_t a_row = (uint32_t)(lane & 15);
    uint32_t a_ko  = (uint32_t)((lane >> 4) << 4);                       // bytes
    uint32_t b_row = (uint32_t)((lane & 7) + ((lane >> 4) << 3));
    uint32_t b_ko  = (uint32_t)(((lane >> 3) & 1) << 4);                 // bytes

    int nk = K >> 5;   // >= 16 always
    fill(0, 0);
    fill(1, 1);
    int stage = 0;
    for (int kt = 0; kt < nk; kt++) {
        __pipeline_wait_prior(1);    // stage kt's fill complete
        __syncthreads();             // also: everyone done consuming stage kt-1
        if (kt + 2 < nk) fill((stage + 2 == NSTAGE) ? 0 : ((stage + 2 > NSTAGE) ? stage - 1 : stage + 2), kt + 2);

        uint32_t stg = sb + (uint32_t)(stage * STAGE_B);
        uint32_t aoff = stg + (wm + a_row) * 80 + a_ko;
        uint32_t boff = stg + 2 * TILE_B + (wn + b_row) * 80 + b_ko;
        #pragma unroll
        for (int kk = 0; kk < 2; kk++) {
            uint32_t kb = (uint32_t)(kk * 32);
            uint32_t bh[2][4];
            #pragma unroll
            for (int nf2 = 0; nf2 < 2; nf2++)
                ldmx4(bh[nf2], boff + nf2 * (16 * 80) + kb);
            #pragma unroll
            for (int mf = 0; mf < 4; mf++) {
                uint32_t ah[4], alr[4];
                ldmx4(ah,  aoff + mf * (16 * 80) + kb);
                ldmx4(alr, aoff + TILE_B + mf * (16 * 80) + kb);
                #pragma unroll
                for (int nf = 0; nf < 4; nf++) {
                    const uint32_t* bhp = &bh[nf >> 1][(nf & 1) * 2];
                    mma16816(acc[mf][nf], ah, bhp);
                    mma16816(acc[mf][nf], alr, bhp);
                }
            }
        }
        stage = (stage + 1 == NSTAGE) ? 0 : stage + 1;
    }
}

// ===========================================================================
// Conversion kernels
// ===========================================================================
__global__ __launch_bounds__(256) void k_cvt(const float* __restrict__ src,
                                             __half* __restrict__ hi,
                                             __half* __restrict__ lo, int n)
{
    int i = (blockIdx.x * 256 + threadIdx.x) * 4;
    if (i >= n) return;
    float4 v = *(const float4*)(src + i);
    uint32_t h0, l0, h1, l1;
    pack2h(v.x, v.y, h0, l0);
    pack2h(v.z, v.w, h1, l1);
    *(uint2*)(hi + i) = make_uint2(h0, h1);
    *(uint2*)(lo + i) = make_uint2(l0, l1);
}

__global__ __launch_bounds__(256) void k_cvtH(const float* __restrict__ src,
                                              __half* __restrict__ hi, int n)
{
    int i = (blockIdx.x * 256 + threadIdx.x) * 4;
    if (i >= n) return;
    float4 v = *(const float4*)(src + i);
    __half2 a; a.x = __float2half_rn(v.x); a.y = __float2half_rn(v.y);
    __half2 b; b.x = __float2half_rn(v.z); b.y = __float2half_rn(v.w);
    *(uint2*)(hi + i) = make_uint2(*reinterpret_cast<uint32_t*>(&a),
                                   *reinterpret_cast<uint32_t*>(&b));
}

__global__ __launch_bounds__(256) void k_cvtT(const float* __restrict__ W)
{
    int idx = blockIdx.x * 256 + threadIdx.x;  // idx = e*512 + d
    int e = idx >> 9, d = idx & 511;
    g_Wth[idx] = __float2half_rn(W[d * 512 + e]);
}

// ===========================================================================
// d-GEMM: g_D = Xd*Wd^T + bd (fp32).  grid (4, 128), block 256
// ===========================================================================
__global__ __launch_bounds__(256, 2) void k_lin_d(const float* __restrict__ bias)
{
    extern __shared__ __align__(16) char smem[];
    int row0 = blockIdx.y * 128, col0 = blockIdx.x * 128;
    float acc[4][4][4] = {};
    gemm2(g_Xdh + (size_t)row0 * INF, g_Xdl + (size_t)row0 * INF, INF,
          g_Wdh + (size_t)col0 * INF, INF, INF, smem, acc);

    int tid = threadIdx.x, lane = tid & 31, wid = tid >> 5;
    int wm = (wid & 1) * 64, wn = (wid >> 1) * 32;
    int rb = row0 + wm + (lane >> 2);
    int cb = col0 + wn + 2 * (lane & 3);
    #pragma unroll
    for (int nf = 0; nf < 4; nf++) {
        int c = cb + nf * 8;
        float b0 = bias[c], b1 = bias[c + 1];
        #pragma unroll
        for (int mf = 0; mf < 4; mf++)
            #pragma unroll
            for (int rr = 0; rr < 2; rr++) {
                int r = rb + mf * 16 + rr * 8;
                *(float2*)(g_D + (size_t)r * OFD + c) =
                    make_float2(acc[mf][nf][rr * 2] + b0, acc[mf][nf][rr * 2 + 1] + b1);
            }
    }
}

// ===========================================================================
// u-GEMM + fused gating: u0 = Xu*Wu^T + bu; d1 = d0*sig(u0); u1 = u0*sig(d1);
// writes fp16 splits of d1, u1.  grid (4, 128), block 256
// ===========================================================================
__global__ __launch_bounds__(256, 2) void k_lin_u(const float* __restrict__ bias)
{
    extern __shared__ __align__(16) char smem[];
    int row0 = blockIdx.y * 128, col0 = blockIdx.x * 128;
    float acc[4][4][4] = {};
    gemm2(g_Xuh + (size_t)row0 * UFD, g_Xul + (size_t)row0 * UFD, UFD,
          g_Wuh + (size_t)col0 * UFD, UFD, UFD, smem, acc);

    int tid = threadIdx.x, lane = tid & 31, wid = tid >> 5;
    int wm = (wid & 1) * 64, wn = (wid >> 1) * 32;
    int rb = row0 + wm + (lane >> 2);
    int cb = col0 + wn + 2 * (lane & 3);
    #pragma unroll
    for (int nf = 0; nf < 4; nf++) {
        int c = cb + nf * 8;
        float b0 = bias[c], b1 = bias[c + 1];
        #pragma unroll
        for (int mf = 0; mf < 4; mf++)
            #pragma unroll
            for (int rr = 0; rr < 2; rr++) {
                int r = rb + mf * 16 + rr * 8;
                size_t idx = (size_t)r * OFD + c;
                float2 d4 = *(const float2*)(g_D + idx);
                float u00 = acc[mf][nf][rr * 2]     + b0;
                float u01 = acc[mf][nf][rr * 2 + 1] + b1;
                float d10 = d4.x * sigm(u00);
                float d11 = d4.y * sigm(u01);
                float u10 = u00 * sigm(d10);
                float u11 = u01 * sigm(d11);
                uint32_t hi, lo;
                pack2h(d10, d11, hi, lo);
                *(uint32_t*)(g_Dh + idx) = hi;
                *(uint32_t*)(g_Dl + idx) = lo;
                pack2h(u10, u11, hi, lo);
                *(uint32_t*)(g_Uh + idx) = hi;
                *(uint32_t*)(g_Ul + idx) = lo;
            }
    }
}

// ===========================================================================
// E = D @ W (via W^T), write fp16 split.  grid (4, 128), block 256
// ===========================================================================
__global__ __launch_bounds__(256, 2) void k_e(void)
{
    extern __shared__ __align__(16) char smem[];
    int row0 = blockIdx.y * 128, col0 = blockIdx.x * 128;
    float acc[4][4][4] = {};
    gemm2(g_Dh + (size_t)row0 * OFD, g_Dl + (size_t)row0 * OFD, OFD,
          g_Wth + (size_t)col0 * OFD, OFD, OFD, smem, acc);

    int tid = threadIdx.x, lane = tid & 31, wid = tid >> 5;
    int wm = (wid & 1) * 64, wn = (wid >> 1) * 32;
    int rb = row0 + wm + (lane >> 2);
    int cb = col0 + wn + 2 * (lane & 3);
    #pragma unroll
    for (int mf = 0; mf < 4; mf++)
        #pragma unroll
        for (int nf = 0; nf < 4; nf++)
            #pragma unroll
            for (int rr = 0; rr < 2; rr++) {
                int r = rb + mf * 16 + rr * 8;
                int c = cb + nf * 8;
                uint32_t hi, lo;
                pack2h(acc[mf][nf][rr * 2], acc[mf][nf][rr * 2 + 1], hi, lo);
                *(uint32_t*)(g_Eh + (size_t)r * OFD + c) = hi;
                *(uint32_t*)(g_El + (size_t)r * OFD + c) = lo;
            }
}

// ===========================================================================
// att tile = tanh(E_b @ U_b^T); row/col partial sums.  grid (2 rt, 2 st, 64 b)
// ===========================================================================
__global__ __launch_bounds__(256, 2) void k_att(void)
{
    extern __shared__ __align__(16) char smem[];
    float* srow = (float*)(smem + NSTAGE * STAGE_B);
    float* scol = srow + 128;
    int b = blockIdx.z, st = blockIdx.y, rt = blockIdx.x;
    int tid = threadIdx.x;
    if (tid < 128) { srow[tid] = 0.0f; scol[tid] = 0.0f; }
    // ordered before atomics below by the mainloop's __syncthreads

    float acc[4][4][4] = {};
    size_t ar = (size_t)(b * SEQ + st * 128) * OFD;
    size_t br = (size_t)(b * SEQ + rt * 128) * OFD;
    gemm2(g_Eh + ar, g_El + ar, OFD, g_Uh + br, OFD, OFD, smem, acc);

    int lane = tid & 31, wid = tid >> 5;
    int wm = (wid & 1) * 64, wn = (wid >> 1) * 32;
    int rb = wm + (lane >> 2);
    int cb = wn + 2 * (lane & 3);

    float t[4][4][4];
    #pragma unroll
    for (int mf = 0; mf < 4; mf++)
        #pragma unroll
        for (int nf = 0; nf < 4; nf++)
            #pragma unroll
            for (int e = 0; e < 4; e++)
                t[mf][nf][e] = tanhf(acc[mf][nf][e]);

    #pragma unroll
    for (int mf = 0; mf < 4; mf++) {
        float s0 = 0.0f, s1 = 0.0f;
        #pragma unroll
        for (int nf = 0; nf < 4; nf++) {
            s0 += t[mf][nf][0] + t[mf][nf][1];
            s1 += t[mf][nf][2] + t[mf][nf][3];
        }
        atomicAdd(&srow[rb + mf * 16], s0);
        atomicAdd(&srow[rb + mf * 16 + 8], s1);
    }
    #pragma unroll
    for (int nf = 0; nf < 4; nf++) {
        float c0 = 0.0f, c1 = 0.0f;
        #pragma unroll
        for (int mf = 0; mf < 4; mf++) {
            c0 += t[mf][nf][0] + t[mf][nf][2];
            c1 += t[mf][nf][1] + t[mf][nf][3];
        }
        atomicAdd(&scol[cb + nf * 8], c0);
        atomicAdd(&scol[cb + nf * 8 + 1], c1);
    }
    __syncthreads();

    if (tid < 128) {
        g_rowpart[(size_t)(b * SEQ + st * 128 + tid) * 2 + rt] = srow[tid];
        g_colpart[(size_t)(b * SEQ + rt * 128 + tid) * 2 + st] = scol[tid];
    }
}

// ===========================================================================
// Softmax + weighted sums.  grid (8 colgrp, 64 b), block 256
// ===========================================================================
__global__ __launch_bounds__(256) void k_out(float* __restrict__ out)
{
    int b = blockIdx.y, cg = blockIdx.x, tid = threadIdx.x;
    __shared__ float sd[256], su[256], red[256], psd[256], psu[256];

    {
        const float* rp = &g_rowpart[(size_t)(b * SEQ + tid) * 2];
        sd[tid] = (rp[0] + rp[1]) * (1.0f / 256.0f);
        const float* cp = &g_colpart[(size_t)(b * SEQ + tid) * 2];
        su[tid] = (cp[0] + cp[1]) * (1.0f / 256.0f);
    }
    __syncthreads();

    // softmax sd
    {
        red[tid] = sd[tid]; __syncthreads();
        for (int off = 128; off > 0; off >>= 1) {
            if (tid < off) red[tid] = fmaxf(red[tid], red[tid + off]);
            __syncthreads();
        }
        float mx = red[0]; __syncthreads();
        float e = expf(sd[tid] - mx);
        red[tid] = e; __syncthreads();
        for (int off = 128; off > 0; off >>= 1) {
            if (tid < off) red[tid] += red[tid + off];
            __syncthreads();
        }
        float inv = 1.0f / red[0]; __syncthreads();
        sd[tid] = e * inv;
    }
    __syncthreads();
    // softmax su
    {
        red[tid] = su[tid]; __syncthreads();
        for (int off = 128; off > 0; off >>= 1) {
            if (tid < off) red[tid] = fmaxf(red[tid], red[tid + off]);
            __syncthreads();
        }
        float mx = red[0]; __syncthreads();
        float e = expf(su[tid] - mx);
        red[tid] = e; __syncthreads();
        for (int off = 128; off > 0; off >>= 1) {
            if (tid < off) red[tid] += red[tid + off];
            __syncthreads();
        }
        float inv = 1.0f / red[0]; __syncthreads();
        su[tid] = e * inv;
    }
    __syncthreads();

    int o = cg * 64 + (tid & 63);
    int sseg = tid >> 6;                 // 4 segments of 64 s each
    size_t base = (size_t)(b * SEQ + sseg * 64) * OFD + o;
    float ad = 0.0f, au = 0.0f;
    #pragma unroll 4
    for (int s = 0; s < 64; s++) {
        size_t idx = base + (size_t)s * OFD;
        float dval = __half2float(g_Dh[idx]) + __half2float(g_Dl[idx]);
        float uval = __half2float(g_Uh[idx]) + __half2float(g_Ul[idx]);
        ad += sd[sseg * 64 + s] * dval;
        au += su[sseg * 64 + s] * uval;
    }
    psd[tid] = ad; psu[tid] = au;
    __syncthreads();
    if (tid < 64) {
        float a = psd[tid] + psd[tid + 64] + psd[tid + 128] + psd[tid + 192];
        float u = psu[tid] + psu[tid + 64] + psu[tid + 128] + psu[tid + 192];
        out[(size_t)b * OFD + cg * 64 + tid] = a;
        out[(size_t)BSZ * OFD + (size_t)b * OFD + cg * 64 + tid] = u;
    }
}

// ===========================================================================
extern "C" void kernel_launch(void* const* d_in, const int* in_sizes, int n_in,
                              void* d_out, int out_size)
{
    (void)in_sizes; (void)n_in; (void)out_size;
    const float* Xd = (const float*)d_in[0];
    const float* Xu = (const float*)d_in[1];
    const float* Wd = (const float*)d_in[2];
    const float* bd = (const float*)d_in[3];
    const float* Wu = (const float*)d_in[4];
    const float* bu = (const float*)d_in[5];
    const float* W  = (const float*)d_in[6];
    float* out = (float*)d_out;

    void *pXdh, *pXdl, *pXuh, *pXul, *pWdh, *pWuh;
    cudaGetSymbolAddress(&pXdh, g_Xdh); cudaGetSymbolAddress(&pXdl, g_Xdl);
    cudaGetSymbolAddress(&pXuh, g_Xuh); cudaGetSymbolAddress(&pXul, g_Xul);
    cudaGetSymbolAddress(&pWdh, g_Wdh); cudaGetSymbolAddress(&pWuh, g_Wuh);

    cudaFuncSetAttribute(k_lin_d, cudaFuncAttributeMaxDynamicSharedMemorySize, SMEM_GEMM);
    cudaFuncSetAttribute(k_lin_u, cudaFuncAttributeMaxDynamicSharedMemorySize, SMEM_GEMM);
    cudaFuncSetAttribute(k_e,     cudaFuncAttributeMaxDynamicSharedMemorySize, SMEM_GEMM);
    cudaFuncSetAttribute(k_att,   cudaFuncAttributeMaxDynamicSharedMemorySize, SMEM_ATT);

    k_cvt<<<MROWS*INF/1024, 256>>>(Xd, (__half*)pXdh, (__half*)pXdl, MROWS*INF);
    k_cvt<<<MROWS*UFD/1024, 256>>>(Xu, (__half*)pXuh, (__half*)pXul, MROWS*UFD);
    k_cvtH<<<OFD*INF/1024, 256>>>(Wd, (__half*)pWdh, OFD*INF);
    k_cvtH<<<OFD*UFD/1024, 256>>>(Wu, (__half*)pWuh, OFD*UFD);
    k_cvtT<<<OFD*OFD/256, 256>>>(W);

    dim3 g1(OFD / 128, MROWS / 128);
    k_lin_d<<<g1, 256, SMEM_GEMM>>>(bd);
    k_lin_u<<<g1, 256, SMEM_GEMM>>>(bu);
    k_e<<<g1, 256, SMEM_GEMM>>>();
    dim3 g3(2, 2, BSZ);
    k_att<<<g3, 256, SMEM_ATT>>>();
    dim3 g4(8, BSZ);
    k_out<<<g4, 256>>>(out);
}

// round 10
// speedup vs baseline: 1.4451x; 1.4451x over previous
#include <cuda_runtime.h>
#include <cuda_fp16.h>
#include <cuda_pipeline.h>
#include <math.h>
#include <stdint.h>

#define BSZ 64
#define SEQ 256
#define MROWS (BSZ*SEQ)   // 16384
#define INF 1024
#define UFD 512
#define OFD 512

#define TILE_B  10240     // 128 rows x 80B (32 fp16 + 8 pad)
#define STAGE_B 30720     // 3 tiles (Ah, Al, Bh)
#define SMEM_GEMM (2*STAGE_B)         // 61440
#define SMEM_ATT  (2*STAGE_B + 1024)  // + srow/scol

// ---------------- scratch (__device__ globals; no runtime alloc) ----------------
__device__ __align__(16) float g_D[MROWS*OFD];   // pre-gating linear d
__device__ __align__(16) __half g_Xdh[MROWS*INF];
__device__ __align__(16) __half g_Xdl[MROWS*INF];
__device__ __align__(16) __half g_Xuh[MROWS*UFD];
__device__ __align__(16) __half g_Xul[MROWS*UFD];
__device__ __align__(16) __half g_Wdh[OFD*INF];
__device__ __align__(16) __half g_Wuh[OFD*UFD];
__device__ __align__(16) __half g_Wth[OFD*OFD];   // W^T: Wt[e][d] = W[d][e]
__device__ __align__(16) __half g_Dh[MROWS*OFD];  // gated d, split
__device__ __align__(16) __half g_Dl[MROWS*OFD];
__device__ __align__(16) __half g_Uh[MROWS*OFD];  // gated u, split
__device__ __align__(16) __half g_Ul[MROWS*OFD];
__device__ __align__(16) __half g_Eh[MROWS*OFD];
__device__ __align__(16) __half g_El[MROWS*OFD];
__device__ float g_rowpart[BSZ*SEQ*2];
__device__ float g_colpart[BSZ*SEQ*2];

// ---------------- helpers ----------------
__device__ __forceinline__ uint32_t smem_to_u32(const void* p) {
    uint32_t a;
    asm("{ .reg .u64 t; cvta.to.shared.u64 t, %1; cvt.u32.u64 %0, t; }" : "=r"(a) : "l"(p));
    return a;
}
__device__ __forceinline__ void ldmx4(uint32_t r[4], uint32_t addr) {
    asm volatile("ldmatrix.sync.aligned.m8n8.x4.shared.b16 {%0,%1,%2,%3}, [%4];"
        : "=r"(r[0]), "=r"(r[1]), "=r"(r[2]), "=r"(r[3]) : "r"(addr));
}
__device__ __forceinline__ void mma16816(float c[4], const uint32_t a[4], const uint32_t b[2]) {
    asm volatile("mma.sync.aligned.m16n8k16.row.col.f32.f16.f16.f32 "
        "{%0,%1,%2,%3}, {%4,%5,%6,%7}, {%8,%9}, {%0,%1,%2,%3};"
        : "+f"(c[0]), "+f"(c[1]), "+f"(c[2]), "+f"(c[3])
        : "r"(a[0]), "r"(a[1]), "r"(a[2]), "r"(a[3]), "r"(b[0]), "r"(b[1]));
}
__device__ __forceinline__ float sigm(float x) { return 1.0f / (1.0f + __expf(-x)); }

__device__ __forceinline__ void pack2h(float v0, float v1, uint32_t& hi, uint32_t& lo) {
    __half h0 = __float2half_rn(v0), h1 = __float2half_rn(v1);
    __half2 hh; hh.x = h0; hh.y = h1;
    __half2 ll;
    ll.x = __float2half_rn(v0 - __half2float(h0));
    ll.y = __float2half_rn(v1 - __half2float(h1));
    hi = *reinterpret_cast<uint32_t*>(&hh);
    lo = *reinterpret_cast<uint32_t*>(&ll);
}

// ---------------- mma mainloop: acc[4][4][4] += (Ah+Al)(128xK) * Bh(128xK)^T --------
// Row-major, k contiguous. BM=BN=128, BK=32, 8 warps (2x4), warp tile 64x32.
// R8-proven structure: 2-stage cp.async, prefetch-then-wait, compile-time staging.
__device__ __forceinline__ void gemm2(
    const __half* __restrict__ Ah, const __half* __restrict__ Al, int lda,
    const __half* __restrict__ Bh, int ldb,
    int K, char* smem, float (&acc)[4][4][4])
{
    int tid = threadIdx.x;
    int lane = tid & 31, wid = tid >> 5;
    int wm = (wid & 1) * 64, wn = (wid >> 1) * 32;
    uint32_t sb = smem_to_u32(smem);

    auto fill = [&](int s, int k0) {
        #pragma unroll
        for (int t = 0; t < 3; t++) {
            const __half* bp = (t == 0) ? Ah : (t == 1) ? Al : Bh;
            int ld = (t < 2) ? lda : ldb;
            #pragma unroll
            for (int h = 0; h < 2; h++) {
                int chunk = h * 256 + tid;          // 0..511 = 128 rows x 4 chunks
                int row = chunk >> 2, c4 = chunk & 3;
                __pipeline_memcpy_async(
                    smem + s * STAGE_B + t * TILE_B + row * 80 + c4 * 16,
                    bp + (size_t)row * ld + k0 + c4 * 8, 16);
            }
        }
        __pipeline_commit();
    };

    // per-lane ldmatrix address components
    uint32_t a_row = (uint32_t)(lane & 15);
    uint32_t a_ko  = (uint32_t)((lane >> 4) << 4);                       // bytes
    uint32_t b_row = (uint32_t)((lane & 7) + ((lane >> 4) << 3));
    uint32_t b_ko  = (uint32_t)(((lane >> 3) & 1) << 4);                 // bytes

    int nk = K >> 5;
    fill(0, 0);
    for (int kt = 0; kt < nk; kt++) {
        if (kt + 1 < nk) { fill((kt + 1) & 1, (kt + 1) * 32); __pipeline_wait_prior(1); }
        else             { __pipeline_wait_prior(0); }
        __syncthreads();

        uint32_t stg = sb + (uint32_t)((kt & 1) * STAGE_B);
        uint32_t aoff = stg + (wm + a_row) * 80 + a_ko;
        uint32_t boff = stg + 2 * TILE_B + (wn + b_row) * 80 + b_ko;
        #pragma unroll
        for (int kk = 0; kk < 2; kk++) {
            uint32_t kb = (uint32_t)(kk * 32);
            uint32_t bh[2][4];
            #pragma unroll
            for (int nf2 = 0; nf2 < 2; nf2++)
                ldmx4(bh[nf2], boff + nf2 * (16 * 80) + kb);
            #pragma unroll
            for (int mf = 0; mf < 4; mf++) {
                uint32_t ah[4], alr[4];
                ldmx4(ah,  aoff + mf * (16 * 80) + kb);
                ldmx4(alr, aoff + TILE_B + mf * (16 * 80) + kb);
                #pragma unroll
                for (int nf = 0; nf < 4; nf++) {
                    const uint32_t* bhp = &bh[nf >> 1][(nf & 1) * 2];
                    mma16816(acc[mf][nf], ah, bhp);
                    mma16816(acc[mf][nf], alr, bhp);
                }
            }
        }
        __syncthreads();
    }
}

// ===========================================================================
// Conversion kernels
// ===========================================================================
__global__ __launch_bounds__(256) void k_cvt(const float* __restrict__ src,
                                             __half* __restrict__ hi,
                                             __half* __restrict__ lo, int n)
{
    int i = (blockIdx.x * 256 + threadIdx.x) * 4;
    if (i >= n) return;
    float4 v = *(const float4*)(src + i);
    uint32_t h0, l0, h1, l1;
    pack2h(v.x, v.y, h0, l0);
    pack2h(v.z, v.w, h1, l1);
    *(uint2*)(hi + i) = make_uint2(h0, h1);
    *(uint2*)(lo + i) = make_uint2(l0, l1);
}

__global__ __launch_bounds__(256) void k_cvtH(const float* __restrict__ src,
                                              __half* __restrict__ hi, int n)
{
    int i = (blockIdx.x * 256 + threadIdx.x) * 4;
    if (i >= n) return;
    float4 v = *(const float4*)(src + i);
    __half2 a; a.x = __float2half_rn(v.x); a.y = __float2half_rn(v.y);
    __half2 b; b.x = __float2half_rn(v.z); b.y = __float2half_rn(v.w);
    *(uint2*)(hi + i) = make_uint2(*reinterpret_cast<uint32_t*>(&a),
                                   *reinterpret_cast<uint32_t*>(&b));
}

__global__ __launch_bounds__(256) void k_cvtT(const float* __restrict__ W)
{
    int idx = blockIdx.x * 256 + threadIdx.x;  // idx = e*512 + d
    int e = idx >> 9, d = idx & 511;
    g_Wth[idx] = __float2half_rn(W[d * 512 + e]);
}

// ===========================================================================
// d-GEMM: g_D = Xd*Wd^T + bd (fp32).  grid (4, 128), block 256
// ===========================================================================
__global__ __launch_bounds__(256, 2) void k_lin_d(const float* __restrict__ bias)
{
    extern __shared__ __align__(16) char smem[];
    int row0 = blockIdx.y * 128, col0 = blockIdx.x * 128;
    float acc[4][4][4] = {};
    gemm2(g_Xdh + (size_t)row0 * INF, g_Xdl + (size_t)row0 * INF, INF,
          g_Wdh + (size_t)col0 * INF, INF, INF, smem, acc);

    int tid = threadIdx.x, lane = tid & 31, wid = tid >> 5;
    int wm = (wid & 1) * 64, wn = (wid >> 1) * 32;
    int rb = row0 + wm + (lane >> 2);
    int cb = col0 + wn + 2 * (lane & 3);
    #pragma unroll
    for (int nf = 0; nf < 4; nf++) {
        int c = cb + nf * 8;
        float b0 = bias[c], b1 = bias[c + 1];
        #pragma unroll
        for (int mf = 0; mf < 4; mf++)
            #pragma unroll
            for (int rr = 0; rr < 2; rr++) {
                int r = rb + mf * 16 + rr * 8;
                *(float2*)(g_D + (size_t)r * OFD + c) =
                    make_float2(acc[mf][nf][rr * 2] + b0, acc[mf][nf][rr * 2 + 1] + b1);
            }
    }
}

// ===========================================================================
// u-GEMM + fused gating: u0 = Xu*Wu^T + bu; d1 = d0*sig(u0); u1 = u0*sig(d1);
// writes fp16 splits of d1, u1.  grid (4, 128), block 256
// ===========================================================================
__global__ __launch_bounds__(256, 2) void k_lin_u(const float* __restrict__ bias)
{
    extern __shared__ __align__(16) char smem[];
    int row0 = blockIdx.y * 128, col0 = blockIdx.x * 128;
    float acc[4][4][4] = {};
    gemm2(g_Xuh + (size_t)row0 * UFD, g_Xul + (size_t)row0 * UFD, UFD,
          g_Wuh + (size_t)col0 * UFD, UFD, UFD, smem, acc);

    int tid = threadIdx.x, lane = tid & 31, wid = tid >> 5;
    int wm = (wid & 1) * 64, wn = (wid >> 1) * 32;
    int rb = row0 + wm + (lane >> 2);
    int cb = col0 + wn + 2 * (lane & 3);
    #pragma unroll
    for (int nf = 0; nf < 4; nf++) {
        int c = cb + nf * 8;
        float b0 = bias[c], b1 = bias[c + 1];
        #pragma unroll
        for (int mf = 0; mf < 4; mf++)
            #pragma unroll
            for (int rr = 0; rr < 2; rr++) {
                int r = rb + mf * 16 + rr * 8;
                size_t idx = (size_t)r * OFD + c;
                float2 d4 = *(const float2*)(g_D + idx);
                float u00 = acc[mf][nf][rr * 2]     + b0;
                float u01 = acc[mf][nf][rr * 2 + 1] + b1;
                float d10 = d4.x * sigm(u00);
                float d11 = d4.y * sigm(u01);
                float u10 = u00 * sigm(d10);
                float u11 = u01 * sigm(d11);
                uint32_t hi, lo;
                pack2h(d10, d11, hi, lo);
                *(uint32_t*)(g_Dh + idx) = hi;
                *(uint32_t*)(g_Dl + idx) = lo;
                pack2h(u10, u11, hi, lo);
                *(uint32_t*)(g_Uh + idx) = hi;
                *(uint32_t*)(g_Ul + idx) = lo;
            }
    }
}

// ===========================================================================
// E = D @ W (via W^T), write fp16 split.  grid (4, 128), block 256
// ===========================================================================
__global__ __launch_bounds__(256, 2) void k_e(void)
{
    extern __shared__ __align__(16) char smem[];
    int row0 = blockIdx.y * 128, col0 = blockIdx.x * 128;
    float acc[4][4][4] = {};
    gemm2(g_Dh + (size_t)row0 * OFD, g_Dl + (size_t)row0 * OFD, OFD,
          g_Wth + (size_t)col0 * OFD, OFD, OFD, smem, acc);

    int tid = threadIdx.x, lane = tid & 31, wid = tid >> 5;
    int wm = (wid & 1) * 64, wn = (wid >> 1) * 32;
    int rb = row0 + wm + (lane >> 2);
    int cb = col0 + wn + 2 * (lane & 3);
    #pragma unroll
    for (int mf = 0; mf < 4; mf++)
        #pragma unroll
        for (int nf = 0; nf < 4; nf++)
            #pragma unroll
            for (int rr = 0; rr < 2; rr++) {
                int r = rb + mf * 16 + rr * 8;
                int c = cb + nf * 8;
                uint32_t hi, lo;
                pack2h(acc[mf][nf][rr * 2], acc[mf][nf][rr * 2 + 1], hi, lo);
                *(uint32_t*)(g_Eh + (size_t)r * OFD + c) = hi;
                *(uint32_t*)(g_El + (size_t)r * OFD + c) = lo;
            }
}

// ===========================================================================
// att tile = tanh(E_b @ U_b^T); row/col partial sums.  grid (2 rt, 2 st, 64 b)
// ===========================================================================
__global__ __launch_bounds__(256, 2) void k_att(void)
{
    extern __shared__ __align__(16) char smem[];
    float* srow = (float*)(smem + 2 * STAGE_B);
    float* scol = srow + 128;
    int b = blockIdx.z, st = blockIdx.y, rt = blockIdx.x;
    int tid = threadIdx.x;
    if (tid < 128) { srow[tid] = 0.0f; scol[tid] = 0.0f; }
    // ordered before atomics below by the mainloop's __syncthreads

    float acc[4][4][4] = {};
    size_t ar = (size_t)(b * SEQ + st * 128) * OFD;
    size_t br = (size_t)(b * SEQ + rt * 128) * OFD;
    gemm2(g_Eh + ar, g_El + ar, OFD, g_Uh + br, OFD, OFD, smem, acc);

    int lane = tid & 31, wid = tid >> 5;
    int wm = (wid & 1) * 64, wn = (wid >> 1) * 32;
    int rb = wm + (lane >> 2);
    int cb = wn + 2 * (lane & 3);

    float t[4][4][4];
    #pragma unroll
    for (int mf = 0; mf < 4; mf++)
        #pragma unroll
        for (int nf = 0; nf < 4; nf++)
            #pragma unroll
            for (int e = 0; e < 4; e++)
                t[mf][nf][e] = tanhf(acc[mf][nf][e]);

    #pragma unroll
    for (int mf = 0; mf < 4; mf++) {
        float s0 = 0.0f, s1 = 0.0f;
        #pragma unroll
        for (int nf = 0; nf < 4; nf++) {
            s0 += t[mf][nf][0] + t[mf][nf][1];
            s1 += t[mf][nf][2] + t[mf][nf][3];
        }
        atomicAdd(&srow[rb + mf * 16], s0);
        atomicAdd(&srow[rb + mf * 16 + 8], s1);
    }
    #pragma unroll
    for (int nf = 0; nf < 4; nf++) {
        float c0 = 0.0f, c1 = 0.0f;
        #pragma unroll
        for (int mf = 0; mf < 4; mf++) {
            c0 += t[mf][nf][0] + t[mf][nf][2];
            c1 += t[mf][nf][1] + t[mf][nf][3];
        }
        atomicAdd(&scol[cb + nf * 8], c0);
        atomicAdd(&scol[cb + nf * 8 + 1], c1);
    }
    __syncthreads();

    if (tid < 128) {
        g_rowpart[(size_t)(b * SEQ + st * 128 + tid) * 2 + rt] = srow[tid];
        g_colpart[(size_t)(b * SEQ + rt * 128 + tid) * 2 + st] = scol[tid];
    }
}

// ===========================================================================
// Softmax + weighted sums.  grid (8 colgrp, 64 b), block 256
// ===========================================================================
__global__ __launch_bounds__(256) void k_out(float* __restrict__ out)
{
    int b = blockIdx.y, cg = blockIdx.x, tid = threadIdx.x;
    __shared__ float sd[256], su[256], red[256], psd[256], psu[256];

    {
        const float* rp = &g_rowpart[(size_t)(b * SEQ + tid) * 2];
        sd[tid] = (rp[0] + rp[1]) * (1.0f / 256.0f);
        const float* cp = &g_colpart[(size_t)(b * SEQ + tid) * 2];
        su[tid] = (cp[0] + cp[1]) * (1.0f / 256.0f);
    }
    __syncthreads();

    // softmax sd
    {
        red[tid] = sd[tid]; __syncthreads();
        for (int off = 128; off > 0; off >>= 1) {
            if (tid < off) red[tid] = fmaxf(red[tid], red[tid + off]);
            __syncthreads();
        }
        float mx = red[0]; __syncthreads();
        float e = expf(sd[tid] - mx);
        red[tid] = e; __syncthreads();
        for (int off = 128; off > 0; off >>= 1) {
            if (tid < off) red[tid] += red[tid + off];
            __syncthreads();
        }
        float inv = 1.0f / red[0]; __syncthreads();
        sd[tid] = e * inv;
    }
    __syncthreads();
    // softmax su
    {
        red[tid] = su[tid]; __syncthreads();
        for (int off = 128; off > 0; off >>= 1) {
            if (tid < off) red[tid] = fmaxf(red[tid], red[tid + off]);
            __syncthreads();
        }
        float mx = red[0]; __syncthreads();
        float e = expf(su[tid] - mx);
        red[tid] = e; __syncthreads();
        for (int off = 128; off > 0; off >>= 1) {
            if (tid < off) red[tid] += red[tid + off];
            __syncthreads();
        }
        float inv = 1.0f / red[0]; __syncthreads();
        su[tid] = e * inv;
    }
    __syncthreads();

    int o = cg * 64 + (tid & 63);
    int sseg = tid >> 6;                 // 4 segments of 64 s each
    size_t base = (size_t)(b * SEQ + sseg * 64) * OFD + o;
    float ad = 0.0f, au = 0.0f;
    #pragma unroll 4
    for (int s = 0; s < 64; s++) {
        size_t idx = base + (size_t)s * OFD;
        float dval = __half2float(g_Dh[idx]) + __half2float(g_Dl[idx]);
        float uval = __half2float(g_Uh[idx]) + __half2float(g_Ul[idx]);
        ad += sd[sseg * 64 + s] * dval;
        au += su[sseg * 64 + s] * uval;
    }
    psd[tid] = ad; psu[tid] = au;
    __syncthreads();
    if (tid < 64) {
        float a = psd[tid] + psd[tid + 64] + psd[tid + 128] + psd[tid + 192];
        float u = psu[tid] + psu[tid + 64] + psu[tid + 128] + psu[tid + 192];
        out[(size_t)b * OFD + cg * 64 + tid] = a;
        out[(size_t)BSZ * OFD + (size_t)b * OFD + cg * 64 + tid] = u;
    }
}

// ===========================================================================
extern "C" void kernel_launch(void* const* d_in, const int* in_sizes, int n_in,
                              void* d_out, int out_size)
{
    (void)in_sizes; (void)n_in; (void)out_size;
    const float* Xd = (const float*)d_in[0];
    const float* Xu = (const float*)d_in[1];
    const float* Wd = (const float*)d_in[2];
    const float* bd = (const float*)d_in[3];
    const float* Wu = (const float*)d_in[4];
    const float* bu = (const float*)d_in[5];
    const float* W  = (const float*)d_in[6];
    float* out = (float*)d_out;

    void *pXdh, *pXdl, *pXuh, *pXul, *pWdh, *pWuh;
    cudaGetSymbolAddress(&pXdh, g_Xdh); cudaGetSymbolAddress(&pXdl, g_Xdl);
    cudaGetSymbolAddress(&pXuh, g_Xuh); cudaGetSymbolAddress(&pXul, g_Xul);
    cudaGetSymbolAddress(&pWdh, g_Wdh); cudaGetSymbolAddress(&pWuh, g_Wuh);

    cudaFuncSetAttribute(k_lin_d, cudaFuncAttributeMaxDynamicSharedMemorySize, SMEM_GEMM);
    cudaFuncSetAttribute(k_lin_u, cudaFuncAttributeMaxDynamicSharedMemorySize, SMEM_GEMM);
    cudaFuncSetAttribute(k_e,     cudaFuncAttributeMaxDynamicSharedMemorySize, SMEM_GEMM);
    cudaFuncSetAttribute(k_att,   cudaFuncAttributeMaxDynamicSharedMemorySize, SMEM_ATT);

    k_cvt<<<MROWS*INF/1024, 256>>>(Xd, (__half*)pXdh, (__half*)pXdl, MROWS*INF);
    k_cvt<<<MROWS*UFD/1024, 256>>>(Xu, (__half*)pXuh, (__half*)pXul, MROWS*UFD);
    k_cvtH<<<OFD*INF/1024, 256>>>(Wd, (__half*)pWdh, OFD*INF);
    k_cvtH<<<OFD*UFD/1024, 256>>>(Wu, (__half*)pWuh, OFD*UFD);
    k_cvtT<<<OFD*OFD/256, 256>>>(W);

    dim3 g1(OFD / 128, MROWS / 128);
    k_lin_d<<<g1, 256, SMEM_GEMM>>>(bd);
    k_lin_u<<<g1, 256, SMEM_GEMM>>>(bu);
    k_e<<<g1, 256, SMEM_GEMM>>>();
    dim3 g3(2, 2, BSZ);
    k_att<<<g3, 256, SMEM_ATT>>>();
    dim3 g4(8, BSZ);
    k_out<<<g4, 256>>>(out);
}

// round 11
// speedup vs baseline: 2.2335x; 1.5456x over previous
#include <cuda_runtime.h>
#include <cuda_fp16.h>
#include <cuda_pipeline.h>
#include <math.h>
#include <stdint.h>

#define BSZ 64
#define SEQ 256
#define MROWS (BSZ*SEQ)   // 16384
#define INF 1024
#define UFD 512
#define OFD 512

#define TILE_B  10240     // 128 rows x 80B (32 fp16 + 8 pad)
#define STAGE_B 20480     // 2 tiles (Ah, Bh)
#define SMEM_GEMM (2*STAGE_B)         // 40960
#define SMEM_ATT  (2*STAGE_B + 1024)  // + srow/scol

// ---------------- scratch (__device__ globals; no runtime alloc) ----------------
__device__ __align__(16) float g_D[MROWS*OFD];   // pre-gating linear d
__device__ __align__(16) __half g_Xdh[MROWS*INF];
__device__ __align__(16) __half g_Xuh[MROWS*UFD];
__device__ __align__(16) __half g_Wdh[OFD*INF];
__device__ __align__(16) __half g_Wuh[OFD*UFD];
__device__ __align__(16) __half g_Wth[OFD*OFD];   // W^T: Wt[e][d] = W[d][e]
__device__ __align__(16) __half g_Dh[MROWS*OFD];  // gated d
__device__ __align__(16) __half g_Uh[MROWS*OFD];  // gated u
__device__ __align__(16) __half g_Eh[MROWS*OFD];
__device__ float g_rowpart[BSZ*SEQ*2];
__device__ float g_colpart[BSZ*SEQ*2];

// ---------------- helpers ----------------
__device__ __forceinline__ uint32_t smem_to_u32(const void* p) {
    uint32_t a;
    asm("{ .reg .u64 t; cvta.to.shared.u64 t, %1; cvt.u32.u64 %0, t; }" : "=r"(a) : "l"(p));
    return a;
}
__device__ __forceinline__ void ldmx4(uint32_t r[4], uint32_t addr) {
    asm volatile("ldmatrix.sync.aligned.m8n8.x4.shared.b16 {%0,%1,%2,%3}, [%4];"
        : "=r"(r[0]), "=r"(r[1]), "=r"(r[2]), "=r"(r[3]) : "r"(addr));
}
__device__ __forceinline__ void mma16816(float c[4], const uint32_t a[4], const uint32_t b[2]) {
    asm volatile("mma.sync.aligned.m16n8k16.row.col.f32.f16.f16.f32 "
        "{%0,%1,%2,%3}, {%4,%5,%6,%7}, {%8,%9}, {%0,%1,%2,%3};"
        : "+f"(c[0]), "+f"(c[1]), "+f"(c[2]), "+f"(c[3])
        : "r"(a[0]), "r"(a[1]), "r"(a[2]), "r"(a[3]), "r"(b[0]), "r"(b[1]));
}
__device__ __forceinline__ float sigm(float x) { return 1.0f / (1.0f + __expf(-x)); }

__device__ __forceinline__ uint32_t packh(float v0, float v1) {
    __half2 h; h.x = __float2half_rn(v0); h.y = __float2half_rn(v1);
    return *reinterpret_cast<uint32_t*>(&h);
}

// ---------------- mma mainloop: acc[4][4][4] += Ah(128xK) * Bh(128xK)^T --------
// Row-major, k contiguous. BM=BN=128, BK=32, 8 warps (2x4), warp tile 64x32.
// R8-proven structure: 2-stage cp.async, prefetch-then-wait, compile-time staging.
__device__ __forceinline__ void gemm1(
    const __half* __restrict__ Ah, int lda,
    const __half* __restrict__ Bh, int ldb,
    int K, char* smem, float (&acc)[4][4][4])
{
    int tid = threadIdx.x;
    int lane = tid & 31, wid = tid >> 5;
    int wm = (wid & 1) * 64, wn = (wid >> 1) * 32;
    uint32_t sb = smem_to_u32(smem);

    auto fill = [&](int s, int k0) {
        #pragma unroll
        for (int t = 0; t < 2; t++) {
            const __half* bp = (t == 0) ? Ah : Bh;
            int ld = (t == 0) ? lda : ldb;
            #pragma unroll
            for (int h = 0; h < 2; h++) {
                int chunk = h * 256 + tid;          // 0..511 = 128 rows x 4 chunks
                int row = chunk >> 2, c4 = chunk & 3;
                __pipeline_memcpy_async(
                    smem + s * STAGE_B + t * TILE_B + row * 80 + c4 * 16,
                    bp + (size_t)row * ld + k0 + c4 * 8, 16);
            }
        }
        __pipeline_commit();
    };

    // per-lane ldmatrix address components
    uint32_t a_row = (uint32_t)(lane & 15);
    uint32_t a_ko  = (uint32_t)((lane >> 4) << 4);                       // bytes
    uint32_t b_row = (uint32_t)((lane & 7) + ((lane >> 4) << 3));
    uint32_t b_ko  = (uint32_t)(((lane >> 3) & 1) << 4);                 // bytes

    int nk = K >> 5;
    fill(0, 0);
    for (int kt = 0; kt < nk; kt++) {
        if (kt + 1 < nk) { fill((kt + 1) & 1, (kt + 1) * 32); __pipeline_wait_prior(1); }
        else             { __pipeline_wait_prior(0); }
        __syncthreads();

        uint32_t stg = sb + (uint32_t)((kt & 1) * STAGE_B);
        uint32_t aoff = stg + (wm + a_row) * 80 + a_ko;
        uint32_t boff = stg + TILE_B + (wn + b_row) * 80 + b_ko;
        #pragma unroll
        for (int kk = 0; kk < 2; kk++) {
            uint32_t kb = (uint32_t)(kk * 32);
            uint32_t bh[2][4];
            #pragma unroll
            for (int nf2 = 0; nf2 < 2; nf2++)
                ldmx4(bh[nf2], boff + nf2 * (16 * 80) + kb);
            #pragma unroll
            for (int mf = 0; mf < 4; mf++) {
                uint32_t ah[4];
                ldmx4(ah, aoff + mf * (16 * 80) + kb);
                #pragma unroll
                for (int nf = 0; nf < 4; nf++)
                    mma16816(acc[mf][nf], ah, &bh[nf >> 1][(nf & 1) * 2]);
            }
        }
        __syncthreads();
    }
}

// ===========================================================================
// Conversion kernels
// ===========================================================================
__global__ __launch_bounds__(256) void k_cvtH(const float* __restrict__ src,
                                              __half* __restrict__ hi, int n)
{
    int i = (blockIdx.x * 256 + threadIdx.x) * 4;
    if (i >= n) return;
    float4 v = *(const float4*)(src + i);
    *(uint2*)(hi + i) = make_uint2(packh(v.x, v.y), packh(v.z, v.w));
}

__global__ __launch_bounds__(256) void k_cvtT(const float* __restrict__ W)
{
    int idx = blockIdx.x * 256 + threadIdx.x;  // idx = e*512 + d
    int e = idx >> 9, d = idx & 511;
    g_Wth[idx] = __float2half_rn(W[d * 512 + e]);
}

// ===========================================================================
// d-GEMM: g_D = Xd*Wd^T + bd (fp32).  grid (4, 128), block 256
// ===========================================================================
__global__ __launch_bounds__(256, 2) void k_lin_d(const float* __restrict__ bias)
{
    extern __shared__ __align__(16) char smem[];
    int row0 = blockIdx.y * 128, col0 = blockIdx.x * 128;
    float acc[4][4][4] = {};
    gemm1(g_Xdh + (size_t)row0 * INF, INF,
          g_Wdh + (size_t)col0 * INF, INF, INF, smem, acc);

    int tid = threadIdx.x, lane = tid & 31, wid = tid >> 5;
    int wm = (wid & 1) * 64, wn = (wid >> 1) * 32;
    int rb = row0 + wm + (lane >> 2);
    int cb = col0 + wn + 2 * (lane & 3);
    #pragma unroll
    for (int nf = 0; nf < 4; nf++) {
        int c = cb + nf * 8;
        float b0 = bias[c], b1 = bias[c + 1];
        #pragma unroll
        for (int mf = 0; mf < 4; mf++)
            #pragma unroll
            for (int rr = 0; rr < 2; rr++) {
                int r = rb + mf * 16 + rr * 8;
                *(float2*)(g_D + (size_t)r * OFD + c) =
                    make_float2(acc[mf][nf][rr * 2] + b0, acc[mf][nf][rr * 2 + 1] + b1);
            }
    }
}

// ===========================================================================
// u-GEMM + fused gating: u0 = Xu*Wu^T + bu; d1 = d0*sig(u0); u1 = u0*sig(d1);
// writes fp16 of d1, u1.  grid (4, 128), block 256
// ===========================================================================
__global__ __launch_bounds__(256, 2) void k_lin_u(const float* __restrict__ bias)
{
    extern __shared__ __align__(16) char smem[];
    int row0 = blockIdx.y * 128, col0 = blockIdx.x * 128;
    float acc[4][4][4] = {};
    gemm1(g_Xuh + (size_t)row0 * UFD, UFD,
          g_Wuh + (size_t)col0 * UFD, UFD, UFD, smem, acc);

    int tid = threadIdx.x, lane = tid & 31, wid = tid >> 5;
    int wm = (wid & 1) * 64, wn = (wid >> 1) * 32;
    int rb = row0 + wm + (lane >> 2);
    int cb = col0 + wn + 2 * (lane & 3);
    #pragma unroll
    for (int nf = 0; nf < 4; nf++) {
        int c = cb + nf * 8;
        float b0 = bias[c], b1 = bias[c + 1];
        #pragma unroll
        for (int mf = 0; mf < 4; mf++)
            #pragma unroll
            for (int rr = 0; rr < 2; rr++) {
                int r = rb + mf * 16 + rr * 8;
                size_t idx = (size_t)r * OFD + c;
                float2 d4 = *(const float2*)(g_D + idx);
                float u00 = acc[mf][nf][rr * 2]     + b0;
                float u01 = acc[mf][nf][rr * 2 + 1] + b1;
                float d10 = d4.x * sigm(u00);
                float d11 = d4.y * sigm(u01);
                float u10 = u00 * sigm(d10);
                float u11 = u01 * sigm(d11);
                *(uint32_t*)(g_Dh + idx) = packh(d10, d11);
                *(uint32_t*)(g_Uh + idx) = packh(u10, u11);
            }
    }
}

// ===========================================================================
// E = D @ W (via W^T), write fp16.  grid (4, 128), block 256
// ===========================================================================
__global__ __launch_bounds__(256, 2) void k_e(void)
{
    extern __shared__ __align__(16) char smem[];
    int row0 = blockIdx.y * 128, col0 = blockIdx.x * 128;
    float acc[4][4][4] = {};
    gemm1(g_Dh + (size_t)row0 * OFD, OFD,
          g_Wth + (size_t)col0 * OFD, OFD, OFD, smem, acc);

    int tid = threadIdx.x, lane = tid & 31, wid = tid >> 5;
    int wm = (wid & 1) * 64, wn = (wid >> 1) * 32;
    int rb = row0 + wm + (lane >> 2);
    int cb = col0 + wn + 2 * (lane & 3);
    #pragma unroll
    for (int mf = 0; mf < 4; mf++)
        #pragma unroll
        for (int nf = 0; nf < 4; nf++)
            #pragma unroll
            for (int rr = 0; rr < 2; rr++) {
                int r = rb + mf * 16 + rr * 8;
                int c = cb + nf * 8;
                *(uint32_t*)(g_Eh + (size_t)r * OFD + c) =
                    packh(acc[mf][nf][rr * 2], acc[mf][nf][rr * 2 + 1]);
            }
}

// ===========================================================================
// att tile = tanh(E_b @ U_b^T); row/col partial sums.  grid (2 rt, 2 st, 64 b)
// ===========================================================================
__global__ __launch_bounds__(256, 2) void k_att(void)
{
    extern __shared__ __align__(16) char smem[];
    float* srow = (float*)(smem + 2 * STAGE_B);
    float* scol = srow + 128;
    int b = blockIdx.z, st = blockIdx.y, rt = blockIdx.x;
    int tid = threadIdx.x;
    if (tid < 128) { srow[tid] = 0.0f; scol[tid] = 0.0f; }
    // ordered before atomics below by the mainloop's __syncthreads

    float acc[4][4][4] = {};
    size_t ar = (size_t)(b * SEQ + st * 128) * OFD;
    size_t br = (size_t)(b * SEQ + rt * 128) * OFD;
    gemm1(g_Eh + ar, OFD, g_Uh + br, OFD, OFD, smem, acc);

    int lane = tid & 31, wid = tid >> 5;
    int wm = (wid & 1) * 64, wn = (wid >> 1) * 32;
    int rb = wm + (lane >> 2);
    int cb = wn + 2 * (lane & 3);

    float t[4][4][4];
    #pragma unroll
    for (int mf = 0; mf < 4; mf++)
        #pragma unroll
        for (int nf = 0; nf < 4; nf++)
            #pragma unroll
            for (int e = 0; e < 4; e++)
                t[mf][nf][e] = tanhf(acc[mf][nf][e]);

    #pragma unroll
    for (int mf = 0; mf < 4; mf++) {
        float s0 = 0.0f, s1 = 0.0f;
        #pragma unroll
        for (int nf = 0; nf < 4; nf++) {
            s0 += t[mf][nf][0] + t[mf][nf][1];
            s1 += t[mf][nf][2] + t[mf][nf][3];
        }
        atomicAdd(&srow[rb + mf * 16], s0);
        atomicAdd(&srow[rb + mf * 16 + 8], s1);
    }
    #pragma unroll
    for (int nf = 0; nf < 4; nf++) {
        float c0 = 0.0f, c1 = 0.0f;
        #pragma unroll
        for (int mf = 0; mf < 4; mf++) {
            c0 += t[mf][nf][0] + t[mf][nf][2];
            c1 += t[mf][nf][1] + t[mf][nf][3];
        }
        atomicAdd(&scol[cb + nf * 8], c0);
        atomicAdd(&scol[cb + nf * 8 + 1], c1);
    }
    __syncthreads();

    if (tid < 128) {
        g_rowpart[(size_t)(b * SEQ + st * 128 + tid) * 2 + rt] = srow[tid];
        g_colpart[(size_t)(b * SEQ + rt * 128 + tid) * 2 + st] = scol[tid];
    }
}

// ===========================================================================
// Softmax + weighted sums.  grid (8 colgrp, 64 b), block 256
// ===========================================================================
__global__ __launch_bounds__(256) void k_out(float* __restrict__ out)
{
    int b = blockIdx.y, cg = blockIdx.x, tid = threadIdx.x;
    __shared__ float sd[256], su[256], red[256], psd[256], psu[256];

    {
        const float* rp = &g_rowpart[(size_t)(b * SEQ + tid) * 2];
        sd[tid] = (rp[0] + rp[1]) * (1.0f / 256.0f);
        const float* cp = &g_colpart[(size_t)(b * SEQ + tid) * 2];
        su[tid] = (cp[0] + cp[1]) * (1.0f / 256.0f);
    }
    __syncthreads();

    // softmax sd
    {
        red[tid] = sd[tid]; __syncthreads();
        for (int off = 128; off > 0; off >>= 1) {
            if (tid < off) red[tid] = fmaxf(red[tid], red[tid + off]);
            __syncthreads();
        }
        float mx = red[0]; __syncthreads();
        float e = expf(sd[tid] - mx);
        red[tid] = e; __syncthreads();
        for (int off = 128; off > 0; off >>= 1) {
            if (tid < off) red[tid] += red[tid + off];
            __syncthreads();
        }
        float inv = 1.0f / red[0]; __syncthreads();
        sd[tid] = e * inv;
    }
    __syncthreads();
    // softmax su
    {
        red[tid] = su[tid]; __syncthreads();
        for (int off = 128; off > 0; off >>= 1) {
            if (tid < off) red[tid] = fmaxf(red[tid], red[tid + off]);
            __syncthreads();
        }
        float mx = red[0]; __syncthreads();
        float e = expf(su[tid] - mx);
        red[tid] = e; __syncthreads();
        for (int off = 128; off > 0; off >>= 1) {
            if (tid < off) red[tid] += red[tid + off];
            __syncthreads();
        }
        float inv = 1.0f / red[0]; __syncthreads();
        su[tid] = e * inv;
    }
    __syncthreads();

    int o = cg * 64 + (tid & 63);
    int sseg = tid >> 6;                 // 4 segments of 64 s each
    size_t base = (size_t)(b * SEQ + sseg * 64) * OFD + o;
    float ad = 0.0f, au = 0.0f;
    #pragma unroll 4
    for (int s = 0; s < 64; s++) {
        size_t idx = base + (size_t)s * OFD;
        ad += sd[sseg * 64 + s] * __half2float(g_Dh[idx]);
        au += su[sseg * 64 + s] * __half2float(g_Uh[idx]);
    }
    psd[tid] = ad; psu[tid] = au;
    __syncthreads();
    if (tid < 64) {
        float a = psd[tid] + psd[tid + 64] + psd[tid + 128] + psd[tid + 192];
        float u = psu[tid] + psu[tid + 64] + psu[tid + 128] + psu[tid + 192];
        out[(size_t)b * OFD + cg * 64 + tid] = a;
        out[(size_t)BSZ * OFD + (size_t)b * OFD + cg * 64 + tid] = u;
    }
}

// ===========================================================================
extern "C" void kernel_launch(void* const* d_in, const int* in_sizes, int n_in,
                              void* d_out, int out_size)
{
    (void)in_sizes; (void)n_in; (void)out_size;
    const float* Xd = (const float*)d_in[0];
    const float* Xu = (const float*)d_in[1];
    const float* Wd = (const float*)d_in[2];
    const float* bd = (const float*)d_in[3];
    const float* Wu = (const float*)d_in[4];
    const float* bu = (const float*)d_in[5];
    const float* W  = (const float*)d_in[6];
    float* out = (float*)d_out;

    void *pXdh, *pXuh, *pWdh, *pWuh;
    cudaGetSymbolAddress(&pXdh, g_Xdh);
    cudaGetSymbolAddress(&pXuh, g_Xuh);
    cudaGetSymbolAddress(&pWdh, g_Wdh);
    cudaGetSymbolAddress(&pWuh, g_Wuh);

    cudaFuncSetAttribute(k_lin_d, cudaFuncAttributeMaxDynamicSharedMemorySize, SMEM_GEMM);
    cudaFuncSetAttribute(k_lin_u, cudaFuncAttributeMaxDynamicSharedMemorySize, SMEM_GEMM);
    cudaFuncSetAttribute(k_e,     cudaFuncAttributeMaxDynamicSharedMemorySize, SMEM_GEMM);
    cudaFuncSetAttribute(k_att,   cudaFuncAttributeMaxDynamicSharedMemorySize, SMEM_ATT);

    k_cvtH<<<MROWS*INF/1024, 256>>>(Xd, (__half*)pXdh, MROWS*INF);
    k_cvtH<<<MROWS*UFD/1024, 256>>>(Xu, (__half*)pXuh, MROWS*UFD);
    k_cvtH<<<OFD*INF/1024, 256>>>(Wd, (__half*)pWdh, OFD*INF);
    k_cvtH<<<OFD*UFD/1024, 256>>>(Wu, (__half*)pWuh, OFD*UFD);
    k_cvtT<<<OFD*OFD/256, 256>>>(W);

    dim3 g1(OFD / 128, MROWS / 128);
    k_lin_d<<<g1, 256, SMEM_GEMM>>>(bd);
    k_lin_u<<<g1, 256, SMEM_GEMM>>>(bu);
    k_e<<<g1, 256, SMEM_GEMM>>>();
    dim3 g3(2, 2, BSZ);
    k_att<<<g3, 256, SMEM_ATT>>>();
    dim3 g4(8, BSZ);
    k_out<<<g4, 256>>>(out);
}

// round 12
// speedup vs baseline: 2.4923x; 1.1158x over previous
#include <cuda_runtime.h>
#include <cuda_fp16.h>
#include <cuda_pipeline.h>
#include <math.h>
#include <stdint.h>

#define BSZ 64
#define SEQ 256
#define MROWS (BSZ*SEQ)   // 16384
#define INF 1024
#define UFD 512
#define OFD 512

#define TILE_B  10240     // 128 rows x 80B (32 fp16 + 8 pad)
#define STAGE_B 20480     // 2 tiles (Ah, Bh)
#define STASH_B (64*256*4)                    // 65536: d-acc stash
#define SMEM_GEMM (2*STAGE_B)                 // 40960
#define SMEM_DU   (2*STAGE_B + STASH_B)       // 106496
#define SMEM_ATT  (2*STAGE_B + 1024)          // + srow/scol

// ---------------- scratch (__device__ globals; no runtime alloc) ----------------
__device__ __align__(16) __half g_Xdh[MROWS*INF];
__device__ __align__(16) __half g_Xuh[MROWS*UFD];
__device__ __align__(16) __half g_Wdh[OFD*INF];
__device__ __align__(16) __half g_Wuh[OFD*UFD];
__device__ __align__(16) __half g_Wth[OFD*OFD];   // W^T: Wt[e][d] = W[d][e]
__device__ __align__(16) __half g_Dh[MROWS*OFD];  // gated d
__device__ __align__(16) __half g_Uh[MROWS*OFD];  // gated u
__device__ __align__(16) __half g_Eh[MROWS*OFD];
__device__ float g_rowpart[BSZ*SEQ*2];
__device__ float g_colpart[BSZ*SEQ*2];

// ---------------- helpers ----------------
__device__ __forceinline__ uint32_t smem_to_u32(const void* p) {
    uint32_t a;
    asm("{ .reg .u64 t; cvta.to.shared.u64 t, %1; cvt.u32.u64 %0, t; }" : "=r"(a) : "l"(p));
    return a;
}
__device__ __forceinline__ void ldmx4(uint32_t r[4], uint32_t addr) {
    asm volatile("ldmatrix.sync.aligned.m8n8.x4.shared.b16 {%0,%1,%2,%3}, [%4];"
        : "=r"(r[0]), "=r"(r[1]), "=r"(r[2]), "=r"(r[3]) : "r"(addr));
}
__device__ __forceinline__ void mma16816(float c[4], const uint32_t a[4], const uint32_t b[2]) {
    asm volatile("mma.sync.aligned.m16n8k16.row.col.f32.f16.f16.f32 "
        "{%0,%1,%2,%3}, {%4,%5,%6,%7}, {%8,%9}, {%0,%1,%2,%3};"
        : "+f"(c[0]), "+f"(c[1]), "+f"(c[2]), "+f"(c[3])
        : "r"(a[0]), "r"(a[1]), "r"(a[2]), "r"(a[3]), "r"(b[0]), "r"(b[1]));
}
__device__ __forceinline__ float sigm(float x) { return 1.0f / (1.0f + __expf(-x)); }

__device__ __forceinline__ uint32_t packh(float v0, float v1) {
    __half2 h; h.x = __float2half_rn(v0); h.y = __float2half_rn(v1);
    return *reinterpret_cast<uint32_t*>(&h);
}

// ---------------- mma mainloop: acc[4][4][4] += Ah(128xK) * Bh(128xK)^T --------
// Row-major, k contiguous. BM=BN=128, BK=32, 8 warps (2x4), warp tile 64x32.
// R8-proven structure: 2-stage cp.async, prefetch-then-wait, compile-time staging.
__device__ __forceinline__ void gemm1(
    const __half* __restrict__ Ah, int lda,
    const __half* __restrict__ Bh, int ldb,
    int K, char* smem, float (&acc)[4][4][4])
{
    int tid = threadIdx.x;
    int lane = tid & 31, wid = tid >> 5;
    int wm = (wid & 1) * 64, wn = (wid >> 1) * 32;
    uint32_t sb = smem_to_u32(smem);

    auto fill = [&](int s, int k0) {
        #pragma unroll
        for (int t = 0; t < 2; t++) {
            const __half* bp = (t == 0) ? Ah : Bh;
            int ld = (t == 0) ? lda : ldb;
            #pragma unroll
            for (int h = 0; h < 2; h++) {
                int chunk = h * 256 + tid;          // 0..511 = 128 rows x 4 chunks
                int row = chunk >> 2, c4 = chunk & 3;
                __pipeline_memcpy_async(
                    smem + s * STAGE_B + t * TILE_B + row * 80 + c4 * 16,
                    bp + (size_t)row * ld + k0 + c4 * 8, 16);
            }
        }
        __pipeline_commit();
    };

    // per-lane ldmatrix address components
    uint32_t a_row = (uint32_t)(lane & 15);
    uint32_t a_ko  = (uint32_t)((lane >> 4) << 4);                       // bytes
    uint32_t b_row = (uint32_t)((lane & 7) + ((lane >> 4) << 3));
    uint32_t b_ko  = (uint32_t)(((lane >> 3) & 1) << 4);                 // bytes

    int nk = K >> 5;
    fill(0, 0);
    for (int kt = 0; kt < nk; kt++) {
        if (kt + 1 < nk) { fill((kt + 1) & 1, (kt + 1) * 32); __pipeline_wait_prior(1); }
        else             { __pipeline_wait_prior(0); }
        __syncthreads();

        uint32_t stg = sb + (uint32_t)((kt & 1) * STAGE_B);
        uint32_t aoff = stg + (wm + a_row) * 80 + a_ko;
        uint32_t boff = stg + TILE_B + (wn + b_row) * 80 + b_ko;
        #pragma unroll
        for (int kk = 0; kk < 2; kk++) {
            uint32_t kb = (uint32_t)(kk * 32);
            uint32_t bh[2][4];
            #pragma unroll
            for (int nf2 = 0; nf2 < 2; nf2++)
                ldmx4(bh[nf2], boff + nf2 * (16 * 80) + kb);
            #pragma unroll
            for (int mf = 0; mf < 4; mf++) {
                uint32_t ah[4];
                ldmx4(ah, aoff + mf * (16 * 80) + kb);
                #pragma unroll
                for (int nf = 0; nf < 4; nf++)
                    mma16816(acc[mf][nf], ah, &bh[nf >> 1][(nf & 1) * 2]);
            }
        }
        __syncthreads();
    }
}

// ===========================================================================
// Conversion kernels (merged)
// ===========================================================================
#define NBLK_XD (MROWS*INF/1024)   // 16384
#define NBLK_XU (MROWS*UFD/1024)   // 8192
#define NBLK_WD (OFD*INF/1024)     // 512
#define NBLK_WU (OFD*UFD/1024)     // 256

__global__ __launch_bounds__(256) void k_cvtX(const float* __restrict__ Xd,
                                              const float* __restrict__ Xu)
{
    int blk = blockIdx.x;
    const float* src; __half* dst; int i;
    if (blk < NBLK_XD) { src = Xd; dst = g_Xdh; i = (blk * 256 + threadIdx.x) * 4; }
    else { src = Xu; dst = g_Xuh; i = ((blk - NBLK_XD) * 256 + threadIdx.x) * 4; }
    float4 v = *(const float4*)(src + i);
    *(uint2*)(dst + i) = make_uint2(packh(v.x, v.y), packh(v.z, v.w));
}

__global__ __launch_bounds__(256) void k_cvtW(const float* __restrict__ Wd,
                                              const float* __restrict__ Wu)
{
    int blk = blockIdx.x;
    const float* src; __half* dst; int i;
    if (blk < NBLK_WD) { src = Wd; dst = g_Wdh; i = (blk * 256 + threadIdx.x) * 4; }
    else { src = Wu; dst = g_Wuh; i = ((blk - NBLK_WD) * 256 + threadIdx.x) * 4; }
    float4 v = *(const float4*)(src + i);
    *(uint2*)(dst + i) = make_uint2(packh(v.x, v.y), packh(v.z, v.w));
}

__global__ __launch_bounds__(256) void k_cvtT(const float* __restrict__ W)
{
    int idx = blockIdx.x * 256 + threadIdx.x;  // idx = e*512 + d
    int e = idx >> 9, d = idx & 511;
    g_Wth[idx] = __float2half_rn(W[d * 512 + e]);
}

// ===========================================================================
// Fused d/u GEMMs + gating: d0 = Xd*Wd^T+bd; u0 = Xu*Wu^T+bu;
// d1 = d0*sig(u0); u1 = u0*sig(d1); writes fp16 d1,u1.  grid (4, 128)
// ===========================================================================
__global__ __launch_bounds__(256, 2) void k_du(const float* __restrict__ bd,
                                               const float* __restrict__ bu)
{
    extern __shared__ __align__(16) char smem[];
    float* stash = (float*)(smem + 2 * STAGE_B);   // 64 x 256 floats, [i][tid]
    int tid = threadIdx.x;
    int row0 = blockIdx.y * 128, col0 = blockIdx.x * 128;

    float acc[4][4][4] = {};
    gemm1(g_Xdh + (size_t)row0 * INF, INF,
          g_Wdh + (size_t)col0 * INF, INF, INF, smem, acc);

    // stash d-acc (private slots, conflict-free [i][tid]; no sync needed)
    {
        float* af = &acc[0][0][0];
        #pragma unroll
        for (int i = 0; i < 64; i++) { stash[i * 256 + tid] = af[i]; af[i] = 0.0f; }
    }

    gemm1(g_Xuh + (size_t)row0 * UFD, UFD,
          g_Wuh + (size_t)col0 * UFD, UFD, UFD, smem, acc);

    int lane = tid & 31, wid = tid >> 5;
    int wm = (wid & 1) * 64, wn = (wid >> 1) * 32;
    int rb = row0 + wm + (lane >> 2);
    int cb = col0 + wn + 2 * (lane & 3);
    #pragma unroll
    for (int nf = 0; nf < 4; nf++) {
        int c = cb + nf * 8;
        float bd0 = bd[c], bd1 = bd[c + 1];
        float bu0 = bu[c], bu1 = bu[c + 1];
        #pragma unroll
        for (int mf = 0; mf < 4; mf++)
            #pragma unroll
            for (int rr = 0; rr < 2; rr++) {
                int r = rb + mf * 16 + rr * 8;
                size_t idx = (size_t)r * OFD + c;
                int si = (mf * 4 + nf) * 4 + rr * 2;
                float d00 = stash[si * 256 + tid]       + bd0;
                float d01 = stash[(si + 1) * 256 + tid] + bd1;
                float u00 = acc[mf][nf][rr * 2]     + bu0;
                float u01 = acc[mf][nf][rr * 2 + 1] + bu1;
                float d10 = d00 * sigm(u00);
                float d11 = d01 * sigm(u01);
                float u10 = u00 * sigm(d10);
                float u11 = u01 * sigm(d11);
                *(uint32_t*)(g_Dh + idx) = packh(d10, d11);
                *(uint32_t*)(g_Uh + idx) = packh(u10, u11);
            }
    }
}

// ===========================================================================
// E = D @ W (via W^T), write fp16.  grid (4, 128), block 256
// ===========================================================================
__global__ __launch_bounds__(256, 2) void k_e(void)
{
    extern __shared__ __align__(16) char smem[];
    int row0 = blockIdx.y * 128, col0 = blockIdx.x * 128;
    float acc[4][4][4] = {};
    gemm1(g_Dh + (size_t)row0 * OFD, OFD,
          g_Wth + (size_t)col0 * OFD, OFD, OFD, smem, acc);

    int tid = threadIdx.x, lane = tid & 31, wid = tid >> 5;
    int wm = (wid & 1) * 64, wn = (wid >> 1) * 32;
    int rb = row0 + wm + (lane >> 2);
    int cb = col0 + wn + 2 * (lane & 3);
    #pragma unroll
    for (int mf = 0; mf < 4; mf++)
        #pragma unroll
        for (int nf = 0; nf < 4; nf++)
            #pragma unroll
            for (int rr = 0; rr < 2; rr++) {
                int r = rb + mf * 16 + rr * 8;
                int c = cb + nf * 8;
                *(uint32_t*)(g_Eh + (size_t)r * OFD + c) =
                    packh(acc[mf][nf][rr * 2], acc[mf][nf][rr * 2 + 1]);
            }
}

// ===========================================================================
// att tile = tanh(E_b @ U_b^T); row/col partial sums.  grid (2 rt, 2 st, 64 b)
// ===========================================================================
__global__ __launch_bounds__(256, 2) void k_att(void)
{
    extern __shared__ __align__(16) char smem[];
    float* srow = (float*)(smem + 2 * STAGE_B);
    float* scol = srow + 128;
    int b = blockIdx.z, st = blockIdx.y, rt = blockIdx.x;
    int tid = threadIdx.x;
    if (tid < 128) { srow[tid] = 0.0f; scol[tid] = 0.0f; }
    // ordered before atomics below by the mainloop's __syncthreads

    float acc[4][4][4] = {};
    size_t ar = (size_t)(b * SEQ + st * 128) * OFD;
    size_t br = (size_t)(b * SEQ + rt * 128) * OFD;
    gemm1(g_Eh + ar, OFD, g_Uh + br, OFD, OFD, smem, acc);

    int lane = tid & 31, wid = tid >> 5;
    int wm = (wid & 1) * 64, wn = (wid >> 1) * 32;
    int rb = wm + (lane >> 2);
    int cb = wn + 2 * (lane & 3);

    float t[4][4][4];
    #pragma unroll
    for (int mf = 0; mf < 4; mf++)
        #pragma unroll
        for (int nf = 0; nf < 4; nf++)
            #pragma unroll
            for (int e = 0; e < 4; e++)
                t[mf][nf][e] = tanhf(acc[mf][nf][e]);

    #pragma unroll
    for (int mf = 0; mf < 4; mf++) {
        float s0 = 0.0f, s1 = 0.0f;
        #pragma unroll
        for (int nf = 0; nf < 4; nf++) {
            s0 += t[mf][nf][0] + t[mf][nf][1];
            s1 += t[mf][nf][2] + t[mf][nf][3];
        }
        atomicAdd(&srow[rb + mf * 16], s0);
        atomicAdd(&srow[rb + mf * 16 + 8], s1);
    }
    #pragma unroll
    for (int nf = 0; nf < 4; nf++) {
        float c0 = 0.0f, c1 = 0.0f;
        #pragma unroll
        for (int mf = 0; mf < 4; mf++) {
            c0 += t[mf][nf][0] + t[mf][nf][2];
            c1 += t[mf][nf][1] + t[mf][nf][3];
        }
        atomicAdd(&scol[cb + nf * 8], c0);
        atomicAdd(&scol[cb + nf * 8 + 1], c1);
    }
    __syncthreads();

    if (tid < 128) {
        g_rowpart[(size_t)(b * SEQ + st * 128 + tid) * 2 + rt] = srow[tid];
        g_colpart[(size_t)(b * SEQ + rt * 128 + tid) * 2 + st] = scol[tid];
    }
}

// ===========================================================================
// Softmax + weighted sums.  grid (8 colgrp, 64 b), block 256
// ===========================================================================
__global__ __launch_bounds__(256) void k_out(float* __restrict__ out)
{
    int b = blockIdx.y, cg = blockIdx.x, tid = threadIdx.x;
    __shared__ float sd[256], su[256], red[256], psd[256], psu[256];

    {
        const float* rp = &g_rowpart[(size_t)(b * SEQ + tid) * 2];
        sd[tid] = (rp[0] + rp[1]) * (1.0f / 256.0f);
        const float* cp = &g_colpart[(size_t)(b * SEQ + tid) * 2];
        su[tid] = (cp[0] + cp[1]) * (1.0f / 256.0f);
    }
    __syncthreads();

    // softmax sd
    {
        red[tid] = sd[tid]; __syncthreads();
        for (int off = 128; off > 0; off >>= 1) {
            if (tid < off) red[tid] = fmaxf(red[tid], red[tid + off]);
            __syncthreads();
        }
        float mx = red[0]; __syncthreads();
        float e = expf(sd[tid] - mx);
        red[tid] = e; __syncthreads();
        for (int off = 128; off > 0; off >>= 1) {
            if (tid < off) red[tid] += red[tid + off];
            __syncthreads();
        }
        float inv = 1.0f / red[0]; __syncthreads();
        sd[tid] = e * inv;
    }
    __syncthreads();
    // softmax su
    {
        red[tid] = su[tid]; __syncthreads();
        for (int off = 128; off > 0; off >>= 1) {
            if (tid < off) red[tid] = fmaxf(red[tid], red[tid + off]);
            __syncthreads();
        }
        float mx = red[0]; __syncthreads();
        float e = expf(su[tid] - mx);
        red[tid] = e; __syncthreads();
        for (int off = 128; off > 0; off >>= 1) {
            if (tid < off) red[tid] += red[tid + off];
            __syncthreads();
        }
        float inv = 1.0f / red[0]; __syncthreads();
        su[tid] = e * inv;
    }
    __syncthreads();

    int o = cg * 64 + (tid & 63);
    int sseg = tid >> 6;                 // 4 segments of 64 s each
    size_t base = (size_t)(b * SEQ + sseg * 64) * OFD + o;
    float ad = 0.0f, au = 0.0f;
    #pragma unroll 4
    for (int s = 0; s < 64; s++) {
        size_t idx = base + (size_t)s * OFD;
        ad += sd[sseg * 64 + s] * __half2float(g_Dh[idx]);
        au += su[sseg * 64 + s] * __half2float(g_Uh[idx]);
    }
    psd[tid] = ad; psu[tid] = au;
    __syncthreads();
    if (tid < 64) {
        float a = psd[tid] + psd[tid + 64] + psd[tid + 128] + psd[tid + 192];
        float u = psu[tid] + psu[tid + 64] + psu[tid + 128] + psu[tid + 192];
        out[(size_t)b * OFD + cg * 64 + tid] = a;
        out[(size_t)BSZ * OFD + (size_t)b * OFD + cg * 64 + tid] = u;
    }
}

// ===========================================================================
extern "C" void kernel_launch(void* const* d_in, const int* in_sizes, int n_in,
                              void* d_out, int out_size)
{
    (void)in_sizes; (void)n_in; (void)out_size;
    const float* Xd = (const float*)d_in[0];
    const float* Xu = (const float*)d_in[1];
    const float* Wd = (const float*)d_in[2];
    const float* bd = (const float*)d_in[3];
    const float* Wu = (const float*)d_in[4];
    const float* bu = (const float*)d_in[5];
    const float* W  = (const float*)d_in[6];
    float* out = (float*)d_out;

    cudaFuncSetAttribute(k_du,  cudaFuncAttributeMaxDynamicSharedMemorySize, SMEM_DU);
    cudaFuncSetAttribute(k_e,   cudaFuncAttributeMaxDynamicSharedMemorySize, SMEM_GEMM);
    cudaFuncSetAttribute(k_att, cudaFuncAttributeMaxDynamicSharedMemorySize, SMEM_ATT);

    k_cvtX<<<NBLK_XD + NBLK_XU, 256>>>(Xd, Xu);
    k_cvtW<<<NBLK_WD + NBLK_WU, 256>>>(Wd, Wu);
    k_cvtT<<<OFD*OFD/256, 256>>>(W);

    dim3 g1(OFD / 128, MROWS / 128);
    k_du<<<g1, 256, SMEM_DU>>>(bd, bu);
    k_e<<<g1, 256, SMEM_GEMM>>>();
    dim3 g3(2, 2, BSZ);
    k_att<<<g3, 256, SMEM_ATT>>>();
    dim3 g4(8, BSZ);
    k_out<<<g4, 256>>>(out);
}

// round 13
// speedup vs baseline: 2.6833x; 1.0767x over previous
#include <cuda_runtime.h>
#include <cuda_fp16.h>
#include <cuda_pipeline.h>
#include <math.h>
#include <stdint.h>

#define BSZ 64
#define SEQ 256
#define MROWS (BSZ*SEQ)   // 16384
#define INF 1024
#define UFD 512
#define OFD 512

#define STASH_B (64*256*4)                    // 65536: d-acc stash (fp32)
#define SMEM_DU   (2*(2*128*80) + STASH_B)    // 40960 + 65536 = 106496
#define SMEM_G64  (2*(2*128*144))             // 73728
#define SMEM_ATT  (SMEM_G64 + 1024)           // + srow/scol

// ---------------- scratch (__device__ globals; no runtime alloc) ----------------
__device__ __align__(16) __half g_Xdh[MROWS*INF];
__device__ __align__(16) __half g_Xuh[MROWS*UFD];
__device__ __align__(16) __half g_Wdh[OFD*INF];
__device__ __align__(16) __half g_Wuh[OFD*UFD];
__device__ __align__(16) __half g_Wth[OFD*OFD];   // W^T: Wt[e][d] = W[d][e]
__device__ __align__(16) __half g_Dh[MROWS*OFD];  // gated d
__device__ __align__(16) __half g_Uh[MROWS*OFD];  // gated u
__device__ __align__(16) __half g_Eh[MROWS*OFD];
__device__ float g_rowpart[BSZ*SEQ*2];
__device__ float g_colpart[BSZ*SEQ*2];

// ---------------- helpers ----------------
__device__ __forceinline__ uint32_t smem_to_u32(const void* p) {
    uint32_t a;
    asm("{ .reg .u64 t; cvta.to.shared.u64 t, %1; cvt.u32.u64 %0, t; }" : "=r"(a) : "l"(p));
    return a;
}
__device__ __forceinline__ void ldmx4(uint32_t r[4], uint32_t addr) {
    asm volatile("ldmatrix.sync.aligned.m8n8.x4.shared.b16 {%0,%1,%2,%3}, [%4];"
        : "=r"(r[0]), "=r"(r[1]), "=r"(r[2]), "=r"(r[3]) : "r"(addr));
}
__device__ __forceinline__ void mma16816(float c[4], const uint32_t a[4], const uint32_t b[2]) {
    asm volatile("mma.sync.aligned.m16n8k16.row.col.f32.f16.f16.f32 "
        "{%0,%1,%2,%3}, {%4,%5,%6,%7}, {%8,%9}, {%0,%1,%2,%3};"
        : "+f"(c[0]), "+f"(c[1]), "+f"(c[2]), "+f"(c[3])
        : "r"(a[0]), "r"(a[1]), "r"(a[2]), "r"(a[3]), "r"(b[0]), "r"(b[1]));
}
__device__ __forceinline__ float sigm(float x) { return 1.0f / (1.0f + __expf(-x)); }

__device__ __forceinline__ uint32_t packh(float v0, float v1) {
    __half2 h; h.x = __float2half_rn(v0); h.y = __float2half_rn(v1);
    return *reinterpret_cast<uint32_t*>(&h);
}

// ---------------- mma mainloop: acc[4][4][4] += Ah(128xK) * Bh(128xK)^T --------
// Row-major, k contiguous. BM=BN=128, 8 warps (2x4), warp tile 64x32.
// Templated on BK (k-tile depth). ONE __syncthreads per k-tile:
//   wait(fill kt) -> sync -> fill(kt+1) -> compute(kt)
// fill(kt+1) overwrites the buffer consumed at kt-1; the sync at kt proves all
// warps finished kt-1, so the overwrite is safe.
template<int BK>
__device__ __forceinline__ void gemm1(
    const __half* __restrict__ Ah, int lda,
    const __half* __restrict__ Bh, int ldb,
    int K, char* smem, float (&acc)[4][4][4])
{
    constexpr int ROWB   = BK * 2 + 16;     // bytes per smem row (pad 16)
    constexpr int TILEB  = 128 * ROWB;
    constexpr int STAGEB = 2 * TILEB;
    constexpr int CHUNKS = BK / 8;          // 16B chunks per row
    constexpr int CSHIFT = (CHUNKS == 4) ? 2 : 3;

    int tid = threadIdx.x;
    int lane = tid & 31, wid = tid >> 5;
    int wm = (wid & 1) * 64, wn = (wid >> 1) * 32;
    uint32_t sb = smem_to_u32(smem);

    auto fill = [&](int s, int k0) {
        #pragma unroll
        for (int t = 0; t < 2; t++) {
            const __half* bp = (t == 0) ? Ah : Bh;
            int ld = (t == 0) ? lda : ldb;
            #pragma unroll
            for (int h = 0; h < CHUNKS / 2; h++) {
                int chunk = h * 256 + tid;              // 128 rows x CHUNKS chunks
                int row = chunk >> CSHIFT, c4 = chunk & (CHUNKS - 1);
                __pipeline_memcpy_async(
                    smem + s * STAGEB + t * TILEB + row * ROWB + c4 * 16,
                    bp + (size_t)row * ld + k0 + c4 * 8, 16);
            }
        }
        __pipeline_commit();
    };

    // per-lane ldmatrix address components
    uint32_t a_row = (uint32_t)(lane & 15);
    uint32_t a_ko  = (uint32_t)((lane >> 4) << 4);                       // bytes
    uint32_t b_row = (uint32_t)((lane & 7) + ((lane >> 4) << 3));
    uint32_t b_ko  = (uint32_t)(((lane >> 3) & 1) << 4);                 // bytes

    int nk = K / BK;
    fill(0, 0);
    for (int kt = 0; kt < nk; kt++) {
        __pipeline_wait_prior(0);     // fill(kt) complete
        __syncthreads();              // all warps done consuming buffer (kt-1)&1
        if (kt + 1 < nk) fill((kt + 1) & 1, (kt + 1) * BK);

        uint32_t stg = sb + (uint32_t)((kt & 1) * STAGEB);
        uint32_t aoff = stg + (wm + a_row) * ROWB + a_ko;
        uint32_t boff = stg + TILEB + (wn + b_row) * ROWB + b_ko;
        #pragma unroll
        for (int kk = 0; kk < BK / 16; kk++) {
            uint32_t kb = (uint32_t)(kk * 32);
            uint32_t bh[2][4];
            #pragma unroll
            for (int nf2 = 0; nf2 < 2; nf2++)
                ldmx4(bh[nf2], boff + nf2 * (16 * ROWB) + kb);
            #pragma unroll
            for (int mf = 0; mf < 4; mf++) {
                uint32_t ah[4];
                ldmx4(ah, aoff + mf * (16 * ROWB) + kb);
                #pragma unroll
                for (int nf = 0; nf < 4; nf++)
                    mma16816(acc[mf][nf], ah, &bh[nf >> 1][(nf & 1) * 2]);
            }
        }
    }
    // NOTE: no trailing sync. Callers that reuse the stage buffers rely on the
    // next gemm1's first in-loop sync (fill(0) targets buffer 0; the last tile
    // consumed buffer (nk-1)&1 which is 1 for all our even-nk cases).
}

// ===========================================================================
// Conversion kernels (merged)
// ===========================================================================
#define NBLK_XD (MROWS*INF/1024)   // 16384
#define NBLK_XU (MROWS*UFD/1024)   // 8192
#define NBLK_WD (OFD*INF/1024)     // 512
#define NBLK_WU (OFD*UFD/1024)     // 256

__global__ __launch_bounds__(256) void k_cvtX(const float* __restrict__ Xd,
                                              const float* __restrict__ Xu)
{
    int blk = blockIdx.x;
    const float* src; __half* dst; int i;
    if (blk < NBLK_XD) { src = Xd; dst = g_Xdh; i = (blk * 256 + threadIdx.x) * 4; }
    else { src = Xu; dst = g_Xuh; i = ((blk - NBLK_XD) * 256 + threadIdx.x) * 4; }
    float4 v = *(const float4*)(src + i);
    *(uint2*)(dst + i) = make_uint2(packh(v.x, v.y), packh(v.z, v.w));
}

__global__ __launch_bounds__(256) void k_cvtW(const float* __restrict__ Wd,
                                              const float* __restrict__ Wu)
{
    int blk = blockIdx.x;
    const float* src; __half* dst; int i;
    if (blk < NBLK_WD) { src = Wd; dst = g_Wdh; i = (blk * 256 + threadIdx.x) * 4; }
    else { src = Wu; dst = g_Wuh; i = ((blk - NBLK_WD) * 256 + threadIdx.x) * 4; }
    float4 v = *(const float4*)(src + i);
    *(uint2*)(dst + i) = make_uint2(packh(v.x, v.y), packh(v.z, v.w));
}

__global__ __launch_bounds__(256) void k_cvtT(const float* __restrict__ W)
{
    int idx = blockIdx.x * 256 + threadIdx.x;  // idx = e*512 + d
    int e = idx >> 9, d = idx & 511;
    g_Wth[idx] = __float2half_rn(W[d * 512 + e]);
}

// ===========================================================================
// Fused d/u GEMMs + gating.  grid (4, 128), block 256, BK=32
// ===========================================================================
__global__ __launch_bounds__(256, 2) void k_du(const float* __restrict__ bd,
                                               const float* __restrict__ bu)
{
    extern __shared__ __align__(16) char smem[];
    float* stash = (float*)(smem + 2 * (2 * 128 * 80));   // 64 x 256 floats, [i][tid]
    int tid = threadIdx.x;
    int row0 = blockIdx.y * 128, col0 = blockIdx.x * 128;

    float acc[4][4][4] = {};
    gemm1<32>(g_Xdh + (size_t)row0 * INF, INF,
              g_Wdh + (size_t)col0 * INF, INF, INF, smem, acc);

    // stash d-acc (private slots, conflict-free [i][tid]; no sync needed)
    {
        float* af = &acc[0][0][0];
        #pragma unroll
        for (int i = 0; i < 64; i++) { stash[i * 256 + tid] = af[i]; af[i] = 0.0f; }
    }

    gemm1<32>(g_Xuh + (size_t)row0 * UFD, UFD,
              g_Wuh + (size_t)col0 * UFD, UFD, UFD, smem, acc);

    int lane = tid & 31, wid = tid >> 5;
    int wm = (wid & 1) * 64, wn = (wid >> 1) * 32;
    int rb = row0 + wm + (lane >> 2);
    int cb = col0 + wn + 2 * (lane & 3);
    #pragma unroll
    for (int nf = 0; nf < 4; nf++) {
        int c = cb + nf * 8;
        float bd0 = bd[c], bd1 = bd[c + 1];
        float bu0 = bu[c], bu1 = bu[c + 1];
        #pragma unroll
        for (int mf = 0; mf < 4; mf++)
            #pragma unroll
            for (int rr = 0; rr < 2; rr++) {
                int r = rb + mf * 16 + rr * 8;
                size_t idx = (size_t)r * OFD + c;
                int si = (mf * 4 + nf) * 4 + rr * 2;
                float d00 = stash[si * 256 + tid]       + bd0;
                float d01 = stash[(si + 1) * 256 + tid] + bd1;
                float u00 = acc[mf][nf][rr * 2]     + bu0;
                float u01 = acc[mf][nf][rr * 2 + 1] + bu1;
                float d10 = d00 * sigm(u00);
                float d11 = d01 * sigm(u01);
                float u10 = u00 * sigm(d10);
                float u11 = u01 * sigm(d11);
                *(uint32_t*)(g_Dh + idx) = packh(d10, d11);
                *(uint32_t*)(g_Uh + idx) = packh(u10, u11);
            }
    }
}

// ===========================================================================
// E = D @ W (via W^T), write fp16.  grid (4, 128), block 256, BK=64
// ===========================================================================
__global__ __launch_bounds__(256, 2) void k_e(void)
{
    extern __shared__ __align__(16) char smem[];
    int row0 = blockIdx.y * 128, col0 = blockIdx.x * 128;
    float acc[4][4][4] = {};
    gemm1<64>(g_Dh + (size_t)row0 * OFD, OFD,
              g_Wth + (size_t)col0 * OFD, OFD, OFD, smem, acc);

    int tid = threadIdx.x, lane = tid & 31, wid = tid >> 5;
    int wm = (wid & 1) * 64, wn = (wid >> 1) * 32;
    int rb = row0 + wm + (lane >> 2);
    int cb = col0 + wn + 2 * (lane & 3);
    #pragma unroll
    for (int mf = 0; mf < 4; mf++)
        #pragma unroll
        for (int nf = 0; nf < 4; nf++)
            #pragma unroll
            for (int rr = 0; rr < 2; rr++) {
                int r = rb + mf * 16 + rr * 8;
                int c = cb + nf * 8;
                *(uint32_t*)(g_Eh + (size_t)r * OFD + c) =
                    packh(acc[mf][nf][rr * 2], acc[mf][nf][rr * 2 + 1]);
            }
}

// ===========================================================================
// att tile = tanh(E_b @ U_b^T); row/col partial sums.  grid (2,2,64), BK=64
// ===========================================================================
__global__ __launch_bounds__(256, 2) void k_att(void)
{
    extern __shared__ __align__(16) char smem[];
    float* srow = (float*)(smem + SMEM_G64);
    float* scol = srow + 128;
    int b = blockIdx.z, st = blockIdx.y, rt = blockIdx.x;
    int tid = threadIdx.x;
    if (tid < 128) { srow[tid] = 0.0f; scol[tid] = 0.0f; }
    // ordered before atomics below by the mainloop's __syncthreads

    float acc[4][4][4] = {};
    size_t ar = (size_t)(b * SEQ + st * 128) * OFD;
    size_t br = (size_t)(b * SEQ + rt * 128) * OFD;
    gemm1<64>(g_Eh + ar, OFD, g_Uh + br, OFD, OFD, smem, acc);

    int lane = tid & 31, wid = tid >> 5;
    int wm = (wid & 1) * 64, wn = (wid >> 1) * 32;
    int rb = wm + (lane >> 2);
    int cb = wn + 2 * (lane & 3);

    float t[4][4][4];
    #pragma unroll
    for (int mf = 0; mf < 4; mf++)
        #pragma unroll
        for (int nf = 0; nf < 4; nf++)
            #pragma unroll
            for (int e = 0; e < 4; e++)
                t[mf][nf][e] = tanhf(acc[mf][nf][e]);

    #pragma unroll
    for (int mf = 0; mf < 4; mf++) {
        float s0 = 0.0f, s1 = 0.0f;
        #pragma unroll
        for (int nf = 0; nf < 4; nf++) {
            s0 += t[mf][nf][0] + t[mf][nf][1];
            s1 += t[mf][nf][2] + t[mf][nf][3];
        }
        atomicAdd(&srow[rb + mf * 16], s0);
        atomicAdd(&srow[rb + mf * 16 + 8], s1);
    }
    #pragma unroll
    for (int nf = 0; nf < 4; nf++) {
        float c0 = 0.0f, c1 = 0.0f;
        #pragma unroll
        for (int mf = 0; mf < 4; mf++) {
            c0 += t[mf][nf][0] + t[mf][nf][2];
            c1 += t[mf][nf][1] + t[mf][nf][3];
        }
        atomicAdd(&scol[cb + nf * 8], c0);
        atomicAdd(&scol[cb + nf * 8 + 1], c1);
    }
    __syncthreads();

    if (tid < 128) {
        g_rowpart[(size_t)(b * SEQ + st * 128 + tid) * 2 + rt] = srow[tid];
        g_colpart[(size_t)(b * SEQ + rt * 128 + tid) * 2 + st] = scol[tid];
    }
}

// ===========================================================================
// Softmax + weighted sums.  grid (8 colgrp, 64 b), block 256
// ===========================================================================
__global__ __launch_bounds__(256) void k_out(float* __restrict__ out)
{
    int b = blockIdx.y, cg = blockIdx.x, tid = threadIdx.x;
    __shared__ float sd[256], su[256], red[256], psd[256], psu[256];

    {
        const float* rp = &g_rowpart[(size_t)(b * SEQ + tid) * 2];
        sd[tid] = (rp[0] + rp[1]) * (1.0f / 256.0f);
        const float* cp = &g_colpart[(size_t)(b * SEQ + tid) * 2];
        su[tid] = (cp[0] + cp[1]) * (1.0f / 256.0f);
    }
    __syncthreads();

    // softmax sd
    {
        red[tid] = sd[tid]; __syncthreads();
        for (int off = 128; off > 0; off >>= 1) {
            if (tid < off) red[tid] = fmaxf(red[tid], red[tid + off]);
            __syncthreads();
        }
        float mx = red[0]; __syncthreads();
        float e = expf(sd[tid] - mx);
        red[tid] = e; __syncthreads();
        for (int off = 128; off > 0; off >>= 1) {
            if (tid < off) red[tid] += red[tid + off];
            __syncthreads();
        }
        float inv = 1.0f / red[0]; __syncthreads();
        sd[tid] = e * inv;
    }
    __syncthreads();
    // softmax su
    {
        red[tid] = su[tid]; __syncthreads();
        for (int off = 128; off > 0; off >>= 1) {
            if (tid < off) red[tid] = fmaxf(red[tid], red[tid + off]);
            __syncthreads();
        }
        float mx = red[0]; __syncthreads();
        float e = expf(su[tid] - mx);
        red[tid] = e; __syncthreads();
        for (int off = 128; off > 0; off >>= 1) {
            if (tid < off) red[tid] += red[tid + off];
            __syncthreads();
        }
        float inv = 1.0f / red[0]; __syncthreads();
        su[tid] = e * inv;
    }
    __syncthreads();

    int o = cg * 64 + (tid & 63);
    int sseg = tid >> 6;                 // 4 segments of 64 s each
    size_t base = (size_t)(b * SEQ + sseg * 64) * OFD + o;
    float ad = 0.0f, au = 0.0f;
    #pragma unroll 4
    for (int s = 0; s < 64; s++) {
        size_t idx = base + (size_t)s * OFD;
        ad += sd[sseg * 64 + s] * __half2float(g_Dh[idx]);
        au += su[sseg * 64 + s] * __half2float(g_Uh[idx]);
    }
    psd[tid] = ad; psu[tid] = au;
    __syncthreads();
    if (tid < 64) {
        float a = psd[tid] + psd[tid + 64] + psd[tid + 128] + psd[tid + 192];
        float u = psu[tid] + psu[tid + 64] + psu[tid + 128] + psu[tid + 192];
        out[(size_t)b * OFD + cg * 64 + tid] = a;
        out[(size_t)BSZ * OFD + (size_t)b * OFD + cg * 64 + tid] = u;
    }
}

// ===========================================================================
extern "C" void kernel_launch(void* const* d_in, const int* in_sizes, int n_in,
                              void* d_out, int out_size)
{
    (void)in_sizes; (void)n_in; (void)out_size;
    const float* Xd = (const float*)d_in[0];
    const float* Xu = (const float*)d_in[1];
    const float* Wd = (const float*)d_in[2];
    const float* bd = (const float*)d_in[3];
    const float* Wu = (const float*)d_in[4];
    const float* bu = (const float*)d_in[5];
    const float* W  = (const float*)d_in[6];
    float* out = (float*)d_out;

    cudaFuncSetAttribute(k_du,  cudaFuncAttributeMaxDynamicSharedMemorySize, SMEM_DU);
    cudaFuncSetAttribute(k_e,   cudaFuncAttributeMaxDynamicSharedMemorySize, SMEM_G64);
    cudaFuncSetAttribute(k_att, cudaFuncAttributeMaxDynamicSharedMemorySize, SMEM_ATT);

    k_cvtX<<<NBLK_XD + NBLK_XU, 256>>>(Xd, Xu);
    k_cvtW<<<NBLK_WD + NBLK_WU, 256>>>(Wd, Wu);
    k_cvtT<<<OFD*OFD/256, 256>>>(W);

    dim3 g1(OFD / 128, MROWS / 128);
    k_du<<<g1, 256, SMEM_DU>>>(bd, bu);
    k_e<<<g1, 256, SMEM_G64>>>();
    dim3 g3(2, 2, BSZ);
    k_att<<<g3, 256, SMEM_ATT>>>();
    dim3 g4(8, BSZ);
    k_out<<<g4, 256>>>(out);
}

// round 14
// speedup vs baseline: 2.8335x; 1.0560x over previous
#include <cuda_runtime.h>
#include <cuda_fp16.h>
#include <cuda_pipeline.h>
#include <math.h>
#include <stdint.h>

#define BSZ 64
#define SEQ 256
#define MROWS (BSZ*SEQ)   // 16384
#define INF 1024
#define UFD 512
#define OFD 512

#define STAGE64 (2*128*144)                   // 36864: one 2-tile stage @BK=64
#define STASH_B (32*256*4)                    // 32768: d-acc stash (half2)
#define SMEM_G64  (2*STAGE64)                 // 73728
#define SMEM_DU   (SMEM_G64 + STASH_B)        // 106496
#define SMEM_ATT  (SMEM_G64 + 1024)           // + srow/scol

// ---------------- scratch (__device__ globals; no runtime alloc) ----------------
__device__ __align__(16) __half g_Xdh[MROWS*INF];
__device__ __align__(16) __half g_Xuh[MROWS*UFD];
__device__ __align__(16) __half g_Wdh[OFD*INF];
__device__ __align__(16) __half g_Wuh[OFD*UFD];
__device__ __align__(16) __half g_Wth[OFD*OFD];   // W^T: Wt[e][d] = W[d][e]
__device__ __align__(16) __half g_Dh[MROWS*OFD];  // gated d
__device__ __align__(16) __half g_Uh[MROWS*OFD];  // gated u
__device__ __align__(16) __half g_Eh[MROWS*OFD];
__device__ float g_rowpart[BSZ*SEQ*2];
__device__ float g_colpart[BSZ*SEQ*2];

// ---------------- helpers ----------------
__device__ __forceinline__ uint32_t smem_to_u32(const void* p) {
    uint32_t a;
    asm("{ .reg .u64 t; cvta.to.shared.u64 t, %1; cvt.u32.u64 %0, t; }" : "=r"(a) : "l"(p));
    return a;
}
__device__ __forceinline__ void ldmx4(uint32_t r[4], uint32_t addr) {
    asm volatile("ldmatrix.sync.aligned.m8n8.x4.shared.b16 {%0,%1,%2,%3}, [%4];"
        : "=r"(r[0]), "=r"(r[1]), "=r"(r[2]), "=r"(r[3]) : "r"(addr));
}
__device__ __forceinline__ void mma16816(float c[4], const uint32_t a[4], const uint32_t b[2]) {
    asm volatile("mma.sync.aligned.m16n8k16.row.col.f32.f16.f16.f32 "
        "{%0,%1,%2,%3}, {%4,%5,%6,%7}, {%8,%9}, {%0,%1,%2,%3};"
        : "+f"(c[0]), "+f"(c[1]), "+f"(c[2]), "+f"(c[3])
        : "r"(a[0]), "r"(a[1]), "r"(a[2]), "r"(a[3]), "r"(b[0]), "r"(b[1]));
}
__device__ __forceinline__ float sigm(float x) { return 1.0f / (1.0f + __expf(-x)); }

__device__ __forceinline__ uint32_t packh(float v0, float v1) {
    __half2 h; h.x = __float2half_rn(v0); h.y = __float2half_rn(v1);
    return *reinterpret_cast<uint32_t*>(&h);
}

// ---------------- mma mainloop: acc[4][4][4] += Ah(128xK) * Bh(128xK)^T --------
// Row-major, k contiguous. BM=BN=128, 8 warps (2x4), warp tile 64x32.
// Templated on BK. ONE __syncthreads per k-tile:
//   wait(fill kt) -> sync -> fill(kt+1) -> compute(kt)
template<int BK>
__device__ __forceinline__ void gemm1(
    const __half* __restrict__ Ah, int lda,
    const __half* __restrict__ Bh, int ldb,
    int K, char* smem, float (&acc)[4][4][4])
{
    constexpr int ROWB   = BK * 2 + 16;     // bytes per smem row (pad 16)
    constexpr int TILEB  = 128 * ROWB;
    constexpr int STAGEB = 2 * TILEB;
    constexpr int CHUNKS = BK / 8;          // 16B chunks per row
    constexpr int CSHIFT = (CHUNKS == 4) ? 2 : 3;

    int tid = threadIdx.x;
    int lane = tid & 31, wid = tid >> 5;
    int wm = (wid & 1) * 64, wn = (wid >> 1) * 32;
    uint32_t sb = smem_to_u32(smem);

    auto fill = [&](int s, int k0) {
        #pragma unroll
        for (int t = 0; t < 2; t++) {
            const __half* bp = (t == 0) ? Ah : Bh;
            int ld = (t == 0) ? lda : ldb;
            #pragma unroll
            for (int h = 0; h < CHUNKS / 2; h++) {
                int chunk = h * 256 + tid;              // 128 rows x CHUNKS chunks
                int row = chunk >> CSHIFT, c4 = chunk & (CHUNKS - 1);
                __pipeline_memcpy_async(
                    smem + s * STAGEB + t * TILEB + row * ROWB + c4 * 16,
                    bp + (size_t)row * ld + k0 + c4 * 8, 16);
            }
        }
        __pipeline_commit();
    };

    // per-lane ldmatrix address components
    uint32_t a_row = (uint32_t)(lane & 15);
    uint32_t a_ko  = (uint32_t)((lane >> 4) << 4);                       // bytes
    uint32_t b_row = (uint32_t)((lane & 7) + ((lane >> 4) << 3));
    uint32_t b_ko  = (uint32_t)(((lane >> 3) & 1) << 4);                 // bytes

    int nk = K / BK;
    fill(0, 0);
    for (int kt = 0; kt < nk; kt++) {
        __pipeline_wait_prior(0);     // fill(kt) complete
        __syncthreads();              // all warps done consuming buffer (kt-1)&1
        if (kt + 1 < nk) fill((kt + 1) & 1, (kt + 1) * BK);

        uint32_t stg = sb + (uint32_t)((kt & 1) * STAGEB);
        uint32_t aoff = stg + (wm + a_row) * ROWB + a_ko;
        uint32_t boff = stg + TILEB + (wn + b_row) * ROWB + b_ko;
        #pragma unroll
        for (int kk = 0; kk < BK / 16; kk++) {
            uint32_t kb = (uint32_t)(kk * 32);
            uint32_t bh[2][4];
            #pragma unroll
            for (int nf2 = 0; nf2 < 2; nf2++)
                ldmx4(bh[nf2], boff + nf2 * (16 * ROWB) + kb);
            #pragma unroll
            for (int mf = 0; mf < 4; mf++) {
                uint32_t ah[4];
                ldmx4(ah, aoff + mf * (16 * ROWB) + kb);
                #pragma unroll
                for (int nf = 0; nf < 4; nf++)
                    mma16816(acc[mf][nf], ah, &bh[nf >> 1][(nf & 1) * 2]);
            }
        }
    }
    // No trailing sync: next gemm1's first in-loop sync covers buffer reuse
    // (all our nk are even, so the last-consumed buffer is 1 and the next
    // fill targets buffer 0).
}

// ===========================================================================
// Conversion kernels (merged)
// ===========================================================================
#define NBLK_XD (MROWS*INF/1024)   // 16384
#define NBLK_XU (MROWS*UFD/1024)   // 8192
#define NBLK_WD (OFD*INF/1024)     // 512
#define NBLK_WU (OFD*UFD/1024)     // 256
#define NBLK_WT (OFD*OFD/256)      // 1024

__global__ __launch_bounds__(256) void k_cvtX(const float* __restrict__ Xd,
                                              const float* __restrict__ Xu)
{
    int blk = blockIdx.x;
    const float* src; __half* dst; int i;
    if (blk < NBLK_XD) { src = Xd; dst = g_Xdh; i = (blk * 256 + threadIdx.x) * 4; }
    else { src = Xu; dst = g_Xuh; i = ((blk - NBLK_XD) * 256 + threadIdx.x) * 4; }
    float4 v = *(const float4*)(src + i);
    *(uint2*)(dst + i) = make_uint2(packh(v.x, v.y), packh(v.z, v.w));
}

__global__ __launch_bounds__(256) void k_cvtW(const float* __restrict__ Wd,
                                              const float* __restrict__ Wu,
                                              const float* __restrict__ W)
{
    int blk = blockIdx.x;
    if (blk < NBLK_WD + NBLK_WU) {
        const float* src; __half* dst; int i;
        if (blk < NBLK_WD) { src = Wd; dst = g_Wdh; i = (blk * 256 + threadIdx.x) * 4; }
        else { src = Wu; dst = g_Wuh; i = ((blk - NBLK_WD) * 256 + threadIdx.x) * 4; }
        float4 v = *(const float4*)(src + i);
        *(uint2*)(dst + i) = make_uint2(packh(v.x, v.y), packh(v.z, v.w));
    } else {
        int idx = (blk - NBLK_WD - NBLK_WU) * 256 + threadIdx.x;  // idx = e*512 + d
        int e = idx >> 9, d = idx & 511;
        g_Wth[idx] = __float2half_rn(W[d * 512 + e]);
    }
}

// ===========================================================================
// Fused d/u GEMMs + gating.  grid (4, 128), block 256, BK=64
// d-acc stashed as half2 (fp16) between the two GEMMs.
// ===========================================================================
__global__ __launch_bounds__(256, 2) void k_du(const float* __restrict__ bd,
                                               const float* __restrict__ bu)
{
    extern __shared__ __align__(16) char smem[];
    __half2* stash = (__half2*)(smem + SMEM_G64);   // 32 x 256 half2, [j][tid]
    int tid = threadIdx.x;
    int row0 = blockIdx.y * 128, col0 = blockIdx.x * 128;

    float acc[4][4][4] = {};
    gemm1<64>(g_Xdh + (size_t)row0 * INF, INF,
              g_Wdh + (size_t)col0 * INF, INF, INF, smem, acc);

    // stash d-acc as half2 (private slots, conflict-free [j][tid]; no sync)
    {
        float* af = &acc[0][0][0];
        #pragma unroll
        for (int j = 0; j < 32; j++) {
            stash[j * 256 + tid] = __floats2half2_rn(af[2 * j], af[2 * j + 1]);
            af[2 * j] = 0.0f; af[2 * j + 1] = 0.0f;
        }
    }

    gemm1<64>(g_Xuh + (size_t)row0 * UFD, UFD,
              g_Wuh + (size_t)col0 * UFD, UFD, UFD, smem, acc);

    int lane = tid & 31, wid = tid >> 5;
    int wm = (wid & 1) * 64, wn = (wid >> 1) * 32;
    int rb = row0 + wm + (lane >> 2);
    int cb = col0 + wn + 2 * (lane & 3);
    #pragma unroll
    for (int nf = 0; nf < 4; nf++) {
        int c = cb + nf * 8;
        float bd0 = bd[c], bd1 = bd[c + 1];
        float bu0 = bu[c], bu1 = bu[c + 1];
        #pragma unroll
        for (int mf = 0; mf < 4; mf++)
            #pragma unroll
            for (int rr = 0; rr < 2; rr++) {
                int r = rb + mf * 16 + rr * 8;
                size_t idx = (size_t)r * OFD + c;
                int si = (mf * 4 + nf) * 4 + rr * 2;       // even
                float2 dp = __half22float2(stash[(si >> 1) * 256 + tid]);
                float d00 = dp.x + bd0;
                float d01 = dp.y + bd1;
                float u00 = acc[mf][nf][rr * 2]     + bu0;
                float u01 = acc[mf][nf][rr * 2 + 1] + bu1;
                float d10 = d00 * sigm(u00);
                float d11 = d01 * sigm(u01);
                float u10 = u00 * sigm(d10);
                float u11 = u01 * sigm(d11);
                *(uint32_t*)(g_Dh + idx) = packh(d10, d11);
                *(uint32_t*)(g_Uh + idx) = packh(u10, u11);
            }
    }
}

// ===========================================================================
// E = D @ W (via W^T), write fp16.  grid (4, 128), block 256, BK=64
// ===========================================================================
__global__ __launch_bounds__(256, 2) void k_e(void)
{
    extern __shared__ __align__(16) char smem[];
    int row0 = blockIdx.y * 128, col0 = blockIdx.x * 128;
    float acc[4][4][4] = {};
    gemm1<64>(g_Dh + (size_t)row0 * OFD, OFD,
              g_Wth + (size_t)col0 * OFD, OFD, OFD, smem, acc);

    int tid = threadIdx.x, lane = tid & 31, wid = tid >> 5;
    int wm = (wid & 1) * 64, wn = (wid >> 1) * 32;
    int rb = row0 + wm + (lane >> 2);
    int cb = col0 + wn + 2 * (lane & 3);
    #pragma unroll
    for (int mf = 0; mf < 4; mf++)
        #pragma unroll
        for (int nf = 0; nf < 4; nf++)
            #pragma unroll
            for (int rr = 0; rr < 2; rr++) {
                int r = rb + mf * 16 + rr * 8;
                int c = cb + nf * 8;
                *(uint32_t*)(g_Eh + (size_t)r * OFD + c) =
                    packh(acc[mf][nf][rr * 2], acc[mf][nf][rr * 2 + 1]);
            }
}

// ===========================================================================
// att tile = tanh(E_b @ U_b^T); row/col partial sums.  grid (2,2,64), BK=64
// ===========================================================================
__global__ __launch_bounds__(256, 2) void k_att(void)
{
    extern __shared__ __align__(16) char smem[];
    float* srow = (float*)(smem + SMEM_G64);
    float* scol = srow + 128;
    int b = blockIdx.z, st = blockIdx.y, rt = blockIdx.x;
    int tid = threadIdx.x;
    if (tid < 128) { srow[tid] = 0.0f; scol[tid] = 0.0f; }
    // ordered before atomics below by the mainloop's __syncthreads

    float acc[4][4][4] = {};
    size_t ar = (size_t)(b * SEQ + st * 128) * OFD;
    size_t br = (size_t)(b * SEQ + rt * 128) * OFD;
    gemm1<64>(g_Eh + ar, OFD, g_Uh + br, OFD, OFD, smem, acc);

    int lane = tid & 31, wid = tid >> 5;
    int wm = (wid & 1) * 64, wn = (wid >> 1) * 32;
    int rb = wm + (lane >> 2);
    int cb = wn + 2 * (lane & 3);

    float t[4][4][4];
    #pragma unroll
    for (int mf = 0; mf < 4; mf++)
        #pragma unroll
        for (int nf = 0; nf < 4; nf++)
            #pragma unroll
            for (int e = 0; e < 4; e++)
                t[mf][nf][e] = tanhf(acc[mf][nf][e]);

    #pragma unroll
    for (int mf = 0; mf < 4; mf++) {
        float s0 = 0.0f, s1 = 0.0f;
        #pragma unroll
        for (int nf = 0; nf < 4; nf++) {
            s0 += t[mf][nf][0] + t[mf][nf][1];
            s1 += t[mf][nf][2] + t[mf][nf][3];
        }
        atomicAdd(&srow[rb + mf * 16], s0);
        atomicAdd(&srow[rb + mf * 16 + 8], s1);
    }
    #pragma unroll
    for (int nf = 0; nf < 4; nf++) {
        float c0 = 0.0f, c1 = 0.0f;
        #pragma unroll
        for (int mf = 0; mf < 4; mf++) {
            c0 += t[mf][nf][0] + t[mf][nf][2];
            c1 += t[mf][nf][1] + t[mf][nf][3];
        }
        atomicAdd(&scol[cb + nf * 8], c0);
        atomicAdd(&scol[cb + nf * 8 + 1], c1);
    }
    __syncthreads();

    if (tid < 128) {
        g_rowpart[(size_t)(b * SEQ + st * 128 + tid) * 2 + rt] = srow[tid];
        g_colpart[(size_t)(b * SEQ + rt * 128 + tid) * 2 + st] = scol[tid];
    }
}

// ===========================================================================
// Softmax + weighted sums.  grid (8 colgrp, 64 b), block 256
// ===========================================================================
__global__ __launch_bounds__(256) void k_out(float* __restrict__ out)
{
    int b = blockIdx.y, cg = blockIdx.x, tid = threadIdx.x;
    __shared__ float sd[256], su[256], red[256], psd[256], psu[256];

    {
        const float* rp = &g_rowpart[(size_t)(b * SEQ + tid) * 2];
        sd[tid] = (rp[0] + rp[1]) * (1.0f / 256.0f);
        const float* cp = &g_colpart[(size_t)(b * SEQ + tid) * 2];
        su[tid] = (cp[0] + cp[1]) * (1.0f / 256.0f);
    }
    __syncthreads();

    // softmax sd
    {
        red[tid] = sd[tid]; __syncthreads();
        for (int off = 128; off > 0; off >>= 1) {
            if (tid < off) red[tid] = fmaxf(red[tid], red[tid + off]);
            __syncthreads();
        }
        float mx = red[0]; __syncthreads();
        float e = expf(sd[tid] - mx);
        red[tid] = e; __syncthreads();
        for (int off = 128; off > 0; off >>= 1) {
            if (tid < off) red[tid] += red[tid + off];
            __syncthreads();
        }
        float inv = 1.0f / red[0]; __syncthreads();
        sd[tid] = e * inv;
    }
    __syncthreads();
    // softmax su
    {
        red[tid] = su[tid]; __syncthreads();
        for (int off = 128; off > 0; off >>= 1) {
            if (tid < off) red[tid] = fmaxf(red[tid], red[tid + off]);
            __syncthreads();
        }
        float mx = red[0]; __syncthreads();
        float e = expf(su[tid] - mx);
        red[tid] = e; __syncthreads();
        for (int off = 128; off > 0; off >>= 1) {
            if (tid < off) red[tid] += red[tid + off];
            __syncthreads();
        }
        float inv = 1.0f / red[0]; __syncthreads();
        su[tid] = e * inv;
    }
    __syncthreads();

    int o = cg * 64 + (tid & 63);
    int sseg = tid >> 6;                 // 4 segments of 64 s each
    size_t base = (size_t)(b * SEQ + sseg * 64) * OFD + o;
    float ad = 0.0f, au = 0.0f;
    #pragma unroll 4
    for (int s = 0; s < 64; s++) {
        size_t idx = base + (size_t)s * OFD;
        ad += sd[sseg * 64 + s] * __half2float(g_Dh[idx]);
        au += su[sseg * 64 + s] * __half2float(g_Uh[idx]);
    }
    psd[tid] = ad; psu[tid] = au;
    __syncthreads();
    if (tid < 64) {
        float a = psd[tid] + psd[tid + 64] + psd[tid + 128] + psd[tid + 192];
        float u = psu[tid] + psu[tid + 64] + psu[tid + 128] + psu[tid + 192];
        out[(size_t)b * OFD + cg * 64 + tid] = a;
        out[(size_t)BSZ * OFD + (size_t)b * OFD + cg * 64 + tid] = u;
    }
}

// ===========================================================================
extern "C" void kernel_launch(void* const* d_in, const int* in_sizes, int n_in,
                              void* d_out, int out_size)
{
    (void)in_sizes; (void)n_in; (void)out_size;
    const float* Xd = (const float*)d_in[0];
    const float* Xu = (const float*)d_in[1];
    const float* Wd = (const float*)d_in[2];
    const float* bd = (const float*)d_in[3];
    const float* Wu = (const float*)d_in[4];
    const float* bu = (const float*)d_in[5];
    const float* W  = (const float*)d_in[6];
    float* out = (float*)d_out;

    cudaFuncSetAttribute(k_du,  cudaFuncAttributeMaxDynamicSharedMemorySize, SMEM_DU);
    cudaFuncSetAttribute(k_e,   cudaFuncAttributeMaxDynamicSharedMemorySize, SMEM_G64);
    cudaFuncSetAttribute(k_att, cudaFuncAttributeMaxDynamicSharedMemorySize, SMEM_ATT);

    k_cvtX<<<NBLK_XD + NBLK_XU, 256>>>(Xd, Xu);
    k_cvtW<<<NBLK_WD + NBLK_WU + NBLK_WT, 256>>>(Wd, Wu, W);

    dim3 g1(OFD / 128, MROWS / 128);
    k_du<<<g1, 256, SMEM_DU>>>(bd, bu);
    k_e<<<g1, 256, SMEM_G64>>>();
    dim3 g3(2, 2, BSZ);
    k_att<<<g3, 256, SMEM_ATT>>>();
    dim3 g4(8, BSZ);
    k_out<<<g4, 256>>>(out);
}

// round 16
// speedup vs baseline: 2.9400x; 1.0376x over previous
#include <cuda_runtime.h>
#include <cuda_fp16.h>
#include <cuda_pipeline.h>
#include <math.h>
#include <stdint.h>

#define BSZ 64
#define SEQ 256
#define MROWS (BSZ*SEQ)   // 16384
#define INF 1024
#define UFD 512
#define OFD 512

#define STAGE64 (2*128*144)                   // 36864: one 2-tile stage @BK=64
#define STASH_B (32*256*4)                    // 32768: d-acc stash (half2)
#define SMEM_DU   (2*STAGE64 + STASH_B)       // 106496 (2-stage + stash)
#define SMEM_G3   (3*STAGE64)                 // 110592 (3-stage)
#define SMEM_ATT  (SMEM_G3 + 1024)            // 111616

// ---------------- scratch (__device__ globals; no runtime alloc) ----------------
__device__ __align__(16) __half g_Xdh[MROWS*INF];
__device__ __align__(16) __half g_Xuh[MROWS*UFD];
__device__ __align__(16) __half g_Wdh[OFD*INF];
__device__ __align__(16) __half g_Wuh[OFD*UFD];
__device__ __align__(16) __half g_Wth[OFD*OFD];   // W^T: Wt[e][d] = W[d][e]
__device__ __align__(16) __half g_Dh[MROWS*OFD];  // gated d
__device__ __align__(16) __half g_Uh[MROWS*OFD];  // gated u
__device__ __align__(16) __half g_Eh[MROWS*OFD];
__device__ float g_rowpart[BSZ*SEQ*2];
__device__ float g_colpart[BSZ*SEQ*2];

// ---------------- helpers ----------------
__device__ __forceinline__ uint32_t smem_to_u32(const void* p) {
    uint32_t a;
    asm("{ .reg .u64 t; cvta.to.shared.u64 t, %1; cvt.u32.u64 %0, t; }" : "=r"(a) : "l"(p));
    return a;
}
__device__ __forceinline__ void ldmx4(uint32_t r[4], uint32_t addr) {
    asm volatile("ldmatrix.sync.aligned.m8n8.x4.shared.b16 {%0,%1,%2,%3}, [%4];"
        : "=r"(r[0]), "=r"(r[1]), "=r"(r[2]), "=r"(r[3]) : "r"(addr));
}
__device__ __forceinline__ void mma16816(float c[4], const uint32_t a[4], const uint32_t b[2]) {
    asm volatile("mma.sync.aligned.m16n8k16.row.col.f32.f16.f16.f32 "
        "{%0,%1,%2,%3}, {%4,%5,%6,%7}, {%8,%9}, {%0,%1,%2,%3};"
        : "+f"(c[0]), "+f"(c[1]), "+f"(c[2]), "+f"(c[3])
        : "r"(a[0]), "r"(a[1]), "r"(a[2]), "r"(a[3]), "r"(b[0]), "r"(b[1]));
}
__device__ __forceinline__ float sigm(float x) { return 1.0f / (1.0f + __expf(-x)); }
__device__ __forceinline__ float fast_tanh(float x) {
    float y; asm("tanh.approx.f32 %0, %1;" : "=f"(y) : "f"(x)); return y;
}
__device__ __forceinline__ uint32_t packh(float v0, float v1) {
    __half2 h; h.x = __float2half_rn(v0); h.y = __float2half_rn(v1);
    return *reinterpret_cast<uint32_t*>(&h);
}

// ---------------- shared compute body for one BK=64 k-tile ----------------
__device__ __forceinline__ void tile_compute64(
    uint32_t stg, int ROWB, int TILEB,
    uint32_t a_row, uint32_t a_ko, uint32_t b_row, uint32_t b_ko,
    int wm, int wn, float (&acc)[4][4][4])
{
    uint32_t aoff = stg + (wm + a_row) * ROWB + a_ko;
    uint32_t boff = stg + TILEB + (wn + b_row) * ROWB + b_ko;
    #pragma unroll
    for (int kk = 0; kk < 4; kk++) {
        uint32_t kb = (uint32_t)(kk * 32);
        uint32_t bh[2][4];
        #pragma unroll
        for (int nf2 = 0; nf2 < 2; nf2++)
            ldmx4(bh[nf2], boff + nf2 * (16 * ROWB) + kb);
        #pragma unroll
        for (int mf = 0; mf < 4; mf++) {
            uint32_t ah[4];
            ldmx4(ah, aoff + mf * (16 * ROWB) + kb);
            #pragma unroll
            for (int nf = 0; nf < 4; nf++)
                mma16816(acc[mf][nf], ah, &bh[nf >> 1][(nf & 1) * 2]);
        }
    }
}

// ---------------- 2-stage mainloop (runtime K), BK=64 — for k_du ----------------
__device__ __forceinline__ void gemm1(
    const __half* __restrict__ Ah, int lda,
    const __half* __restrict__ Bh, int ldb,
    int K, char* smem, float (&acc)[4][4][4])
{
    constexpr int ROWB = 144, TILEB = 128 * 144, STAGEB = 2 * TILEB;
    int tid = threadIdx.x;
    int lane = tid & 31, wid = tid >> 5;
    int wm = (wid & 1) * 64, wn = (wid >> 1) * 32;
    uint32_t sb = smem_to_u32(smem);

    auto fill = [&](int s, int k0) {
        #pragma unroll
        for (int t = 0; t < 2; t++) {
            const __half* bp = (t == 0) ? Ah : Bh;
            int ld = (t == 0) ? lda : ldb;
            #pragma unroll
            for (int h = 0; h < 4; h++) {
                int chunk = h * 256 + tid;              // 128 rows x 8 chunks
                int row = chunk >> 3, c4 = chunk & 7;
                __pipeline_memcpy_async(
                    smem + s * STAGEB + t * TILEB + row * ROWB + c4 * 16,
                    bp + (size_t)row * ld + k0 + c4 * 8, 16);
            }
        }
        __pipeline_commit();
    };

    uint32_t a_row = (uint32_t)(lane & 15);
    uint32_t a_ko  = (uint32_t)((lane >> 4) << 4);
    uint32_t b_row = (uint32_t)((lane & 7) + ((lane >> 4) << 3));
    uint32_t b_ko  = (uint32_t)(((lane >> 3) & 1) << 4);

    int nk = K >> 6;
    fill(0, 0);
    for (int kt = 0; kt < nk; kt++) {
        __pipeline_wait_prior(0);
        __syncthreads();
        if (kt + 1 < nk) fill((kt + 1) & 1, (kt + 1) * 64);
        tile_compute64(sb + (uint32_t)((kt & 1) * STAGEB), ROWB, TILEB,
                       a_row, a_ko, b_row, b_ko, wm, wn, acc);
    }
    // No trailing sync: next gemm's first in-loop sync covers buffer reuse
    // (nk even -> last-consumed buffer is 1, next fill targets buffer 0).
}

// ---------------- 3-stage fully-unrolled mainloop (K constexpr), BK=64 --------
template<int K>
__device__ __forceinline__ void gemm3(
    const __half* __restrict__ Ah, int lda,
    const __half* __restrict__ Bh, int ldb,
    char* smem, float (&acc)[4][4][4])
{
    constexpr int ROWB = 144, TILEB = 128 * 144, STAGEB = 2 * TILEB;
    constexpr int nk = K / 64;
    int tid = threadIdx.x;
    int lane = tid & 31, wid = tid >> 5;
    int wm = (wid & 1) * 64, wn = (wid >> 1) * 32;
    uint32_t sb = smem_to_u32(smem);

    auto fill = [&](int s, int k0) {
        #pragma unroll
        for (int t = 0; t < 2; t++) {
            const __half* bp = (t == 0) ? Ah : Bh;
            int ld = (t == 0) ? lda : ldb;
            #pragma unroll
            for (int h = 0; h < 4; h++) {
                int chunk = h * 256 + tid;
                int row = chunk >> 3, c4 = chunk & 7;
                __pipeline_memcpy_async(
                    smem + s * STAGEB + t * TILEB + row * ROWB + c4 * 16,
                    bp + (size_t)row * ld + k0 + c4 * 8, 16);
            }
        }
        __pipeline_commit();
    };

    uint32_t a_row = (uint32_t)(lane & 15);
    uint32_t a_ko  = (uint32_t)((lane >> 4) << 4);
    uint32_t b_row = (uint32_t)((lane & 7) + ((lane >> 4) << 3));
    uint32_t b_ko  = (uint32_t)(((lane >> 3) & 1) << 4);

    fill(0, 0);
    fill(1, 64);
    #pragma unroll
    for (int kt = 0; kt < nk; kt++) {
        // wait until fill(kt) complete: after issuing fills 0..min(kt+1,nk-1),
        // leaving 1 pending suffices except on the final tile.
        if (kt + 1 < nk) __pipeline_wait_prior(1);
        else             __pipeline_wait_prior(0);
        __syncthreads();              // all warps done with buffer (kt+2)%3
        if (kt + 2 < nk) fill((kt + 2) % 3, (kt + 2) * 64);
        tile_compute64(sb + (uint32_t)((kt % 3) * STAGEB), ROWB, TILEB,
                       a_row, a_ko, b_row, b_ko, wm, wn, acc);
    }
}

// ===========================================================================
// Single conversion kernel: Xd, Xu, Wd, Wu (straight) + W transpose
// ===========================================================================
#define NBLK_XD (MROWS*INF/1024)   // 16384
#define NBLK_XU (MROWS*UFD/1024)   // 8192
#define NBLK_WD (OFD*INF/1024)     // 512
#define NBLK_WU (OFD*UFD/1024)     // 256
#define NBLK_WT (OFD*OFD/256)      // 1024
#define NBLK_CVT (NBLK_XD + NBLK_XU + NBLK_WD + NBLK_WU + NBLK_WT)

__global__ __launch_bounds__(256) void k_cvt(
    const float* __restrict__ Xd, const float* __restrict__ Xu,
    const float* __restrict__ Wd, const float* __restrict__ Wu,
    const float* __restrict__ W)
{
    int blk = blockIdx.x;
    if (blk < NBLK_XD + NBLK_XU + NBLK_WD + NBLK_WU) {
        const float* src; __half* dst; int i;
        if (blk < NBLK_XD) { src = Xd; dst = g_Xdh; i = blk; }
        else if (blk < NBLK_XD + NBLK_XU) { src = Xu; dst = g_Xuh; i = blk - NBLK_XD; }
        else if (blk < NBLK_XD + NBLK_XU + NBLK_WD) { src = Wd; dst = g_Wdh; i = blk - NBLK_XD - NBLK_XU; }
        else { src = Wu; dst = g_Wuh; i = blk - NBLK_XD - NBLK_XU - NBLK_WD; }
        int idx = (i * 256 + threadIdx.x) * 4;
        float4 v = *(const float4*)(src + idx);
        *(uint2*)(dst + idx) = make_uint2(packh(v.x, v.y), packh(v.z, v.w));
    } else {
        int idx = (blk - (NBLK_CVT - NBLK_WT)) * 256 + threadIdx.x;  // = e*512 + d
        int e = idx >> 9, d = idx & 511;
        g_Wth[idx] = __float2half_rn(W[d * 512 + e]);
    }
}

// ===========================================================================
// Fused d/u GEMMs + gating.  grid (4, 128), block 256, BK=64, 2-stage
// ===========================================================================
__global__ __launch_bounds__(256, 2) void k_du(const float* __restrict__ bd,
                                               const float* __restrict__ bu)
{
    extern __shared__ __align__(16) char smem[];
    __half2* stash = (__half2*)(smem + 2 * STAGE64);   // 32 x 256 half2, [j][tid]
    int tid = threadIdx.x;
    int row0 = blockIdx.y * 128, col0 = blockIdx.x * 128;

    float acc[4][4][4] = {};
    gemm1(g_Xdh + (size_t)row0 * INF, INF,
          g_Wdh + (size_t)col0 * INF, INF, INF, smem, acc);

    // stash d-acc as half2 (private slots, conflict-free [j][tid]; no sync)
    {
        float* af = &acc[0][0][0];
        #pragma unroll
        for (int j = 0; j < 32; j++) {
            stash[j * 256 + tid] = __floats2half2_rn(af[2 * j], af[2 * j + 1]);
            af[2 * j] = 0.0f; af[2 * j + 1] = 0.0f;
        }
    }

    gemm1(g_Xuh + (size_t)row0 * UFD, UFD,
          g_Wuh + (size_t)col0 * UFD, UFD, UFD, smem, acc);

    int lane = tid & 31, wid = tid >> 5;
    int wm = (wid & 1) * 64, wn = (wid >> 1) * 32;
    int rb = row0 + wm + (lane >> 2);
    int cb = col0 + wn + 2 * (lane & 3);
    #pragma unroll
    for (int nf = 0; nf < 4; nf++) {
        int c = cb + nf * 8;
        float bd0 = bd[c], bd1 = bd[c + 1];
        float bu0 = bu[c], bu1 = bu[c + 1];
        #pragma unroll
        for (int mf = 0; mf < 4; mf++)
            #pragma unroll
            for (int rr = 0; rr < 2; rr++) {
                int r = rb + mf * 16 + rr * 8;
                size_t idx = (size_t)r * OFD + c;
                int si = (mf * 4 + nf) * 4 + rr * 2;       // even
                float2 dp = __half22float2(stash[(si >> 1) * 256 + tid]);
                float d00 = dp.x + bd0;
                float d01 = dp.y + bd1;
                float u00 = acc[mf][nf][rr * 2]     + bu0;
                float u01 = acc[mf][nf][rr * 2 + 1] + bu1;
                float d10 = d00 * sigm(u00);
                float d11 = d01 * sigm(u01);
                float u10 = u00 * sigm(d10);
                float u11 = u01 * sigm(d11);
                *(uint32_t*)(g_Dh + idx) = packh(d10, d11);
                *(uint32_t*)(g_Uh + idx) = packh(u10, u11);
            }
    }
}

// ===========================================================================
// E = D @ W (via W^T), write fp16.  grid (4, 128), block 256, 3-stage
// ===========================================================================
__global__ __launch_bounds__(256, 2) void k_e(void)
{
    extern __shared__ __align__(16) char smem[];
    int row0 = blockIdx.y * 128, col0 = blockIdx.x * 128;
    float acc[4][4][4] = {};
    gemm3<OFD>(g_Dh + (size_t)row0 * OFD, OFD,
               g_Wth + (size_t)col0 * OFD, OFD, smem, acc);

    int tid = threadIdx.x, lane = tid & 31, wid = tid >> 5;
    int wm = (wid & 1) * 64, wn = (wid >> 1) * 32;
    int rb = row0 + wm + (lane >> 2);
    int cb = col0 + wn + 2 * (lane & 3);
    #pragma unroll
    for (int mf = 0; mf < 4; mf++)
        #pragma unroll
        for (int nf = 0; nf < 4; nf++)
            #pragma unroll
            for (int rr = 0; rr < 2; rr++) {
                int r = rb + mf * 16 + rr * 8;
                int c = cb + nf * 8;
                *(uint32_t*)(g_Eh + (size_t)r * OFD + c) =
                    packh(acc[mf][nf][rr * 2], acc[mf][nf][rr * 2 + 1]);
            }
}

// ===========================================================================
// att tile = tanh(E_b @ U_b^T); row/col partial sums.  grid (2,2,64), 3-stage
// ===========================================================================
__global__ __launch_bounds__(256, 2) void k_att(void)
{
    extern __shared__ __align__(16) char smem[];
    float* srow = (float*)(smem + SMEM_G3);
    float* scol = srow + 128;
    int b = blockIdx.z, st = blockIdx.y, rt = blockIdx.x;
    int tid = threadIdx.x;
    if (tid < 128) { srow[tid] = 0.0f; scol[tid] = 0.0f; }
    // ordered before atomics below by the mainloop's __syncthreads

    float acc[4][4][4] = {};
    size_t ar = (size_t)(b * SEQ + st * 128) * OFD;
    size_t br = (size_t)(b * SEQ + rt * 128) * OFD;
    gemm3<OFD>(g_Eh + ar, OFD, g_Uh + br, OFD, smem, acc);

    int lane = tid & 31, wid = tid >> 5;
    int wm = (wid & 1) * 64, wn = (wid >> 1) * 32;
    int rb = wm + (lane >> 2);
    int cb = wn + 2 * (lane & 3);

    float t[4][4][4];
    #pragma unroll
    for (int mf = 0; mf < 4; mf++)
        #pragma unroll
        for (int nf = 0; nf < 4; nf++)
            #pragma unroll
            for (int e = 0; e < 4; e++)
                t[mf][nf][e] = fast_tanh(acc[mf][nf][e]);

    #pragma unroll
    for (int mf = 0; mf < 4; mf++) {
        float s0 = 0.0f, s1 = 0.0f;
        #pragma unroll
        for (int nf = 0; nf < 4; nf++) {
            s0 += t[mf][nf][0] + t[mf][nf][1];
            s1 += t[mf][nf][2] + t[mf][nf][3];
        }
        atomicAdd(&srow[rb + mf * 16], s0);
        atomicAdd(&srow[rb + mf * 16 + 8], s1);
    }
    #pragma unroll
    for (int nf = 0; nf < 4; nf++) {
        float c0 = 0.0f, c1 = 0.0f;
        #pragma unroll
        for (int mf = 0; mf < 4; mf++) {
            c0 += t[mf][nf][0] + t[mf][nf][2];
            c1 += t[mf][nf][1] + t[mf][nf][3];
        }
        atomicAdd(&scol[cb + nf * 8], c0);
        atomicAdd(&scol[cb + nf * 8 + 1], c1);
    }
    __syncthreads();

    if (tid < 128) {
        g_rowpart[(size_t)(b * SEQ + st * 128 + tid) * 2 + rt] = srow[tid];
        g_colpart[(size_t)(b * SEQ + rt * 128 + tid) * 2 + st] = scol[tid];
    }
}

// ===========================================================================
// Softmax + weighted sums.  grid (8 colgrp, 64 b), block 256
// ===========================================================================
__global__ __launch_bounds__(256) void k_out(float* __restrict__ out)
{
    int b = blockIdx.y, cg = blockIdx.x, tid = threadIdx.x;
    __shared__ float sd[256], su[256], red[256], psd[256], psu[256];

    {
        const float* rp = &g_rowpart[(size_t)(b * SEQ + tid) * 2];
        sd[tid] = (rp[0] + rp[1]) * (1.0f / 256.0f);
        const float* cp = &g_colpart[(size_t)(b * SEQ + tid) * 2];
        su[tid] = (cp[0] + cp[1]) * (1.0f / 256.0f);
    }
    __syncthreads();

    // softmax sd
    {
        red[tid] = sd[tid]; __syncthreads();
        for (int off = 128; off > 0; off >>= 1) {
            if (tid < off) red[tid] = fmaxf(red[tid], red[tid + off]);
            __syncthreads();
        }
        float mx = red[0]; __syncthreads();
        float e = expf(sd[tid] - mx);
        red[tid] = e; __syncthreads();
        for (int off = 128; off > 0; off >>= 1) {
            if (tid < off) red[tid] += red[tid + off];
            __syncthreads();
        }
        float inv = 1.0f / red[0]; __syncthreads();
        sd[tid] = e * inv;
    }
    __syncthreads();
    // softmax su
    {
        red[tid] = su[tid]; __syncthreads();
        for (int off = 128; off > 0; off >>= 1) {
            if (tid < off) red[tid] = fmaxf(red[tid], red[tid + off]);
            __syncthreads();
        }
        float mx = red[0]; __syncthreads();
        float e = expf(su[tid] - mx);
        red[tid] = e; __syncthreads();
        for (int off = 128; off > 0; off >>= 1) {
            if (tid < off) red[tid] += red[tid + off];
            __syncthreads();
        }
        float inv = 1.0f / red[0]; __syncthreads();
        su[tid] = e * inv;
    }
    __syncthreads();

    int o = cg * 64 + (tid & 63);
    int sseg = tid >> 6;                 // 4 segments of 64 s each
    size_t base = (size_t)(b * SEQ + sseg * 64) * OFD + o;
    float ad = 0.0f, au = 0.0f;
    #pragma unroll 4
    for (int s = 0; s < 64; s++) {
        size_t idx = base + (size_t)s * OFD;
        ad += sd[sseg * 64 + s] * __half2float(g_Dh[idx]);
        au += su[sseg * 64 + s] * __half2float(g_Uh[idx]);
    }
    psd[tid] = ad; psu[tid] = au;
    __syncthreads();
    if (tid < 64) {
        float a = psd[tid] + psd[tid + 64] + psd[tid + 128] + psd[tid + 192];
        float u = psu[tid] + psu[tid + 64] + psu[tid + 128] + psu[tid + 192];
        out[(size_t)b * OFD + cg * 64 + tid] = a;
        out[(size_t)BSZ * OFD + (size_t)b * OFD + cg * 64 + tid] = u;
    }
}

// ===========================================================================
extern "C" void kernel_launch(void* const* d_in, const int* in_sizes, int n_in,
                              void* d_out, int out_size)
{
    (void)in_sizes; (void)n_in; (void)out_size;
    const float* Xd = (const float*)d_in[0];
    const float* Xu = (const float*)d_in[1];
    const float* Wd = (const float*)d_in[2];
    const float* bd = (const float*)d_in[3];
    const float* Wu = (const float*)d_in[4];
    const float* bu = (const float*)d_in[5];
    const float* W  = (const float*)d_in[6];
    float* out = (float*)d_out;

    cudaFuncSetAttribute(k_du,  cudaFuncAttributeMaxDynamicSharedMemorySize, SMEM_DU);
    cudaFuncSetAttribute(k_e,   cudaFuncAttributeMaxDynamicSharedMemorySize, SMEM_G3);
    cudaFuncSetAttribute(k_att, cudaFuncAttributeMaxDynamicSharedMemorySize, SMEM_ATT);

    k_cvt<<<NBLK_CVT, 256>>>(Xd, Xu, Wd, Wu, W);

    dim3 g1(OFD / 128, MROWS / 128);
    k_du<<<g1, 256, SMEM_DU>>>(bd, bu);
    k_e<<<g1, 256, SMEM_G3>>>();
    dim3 g3(2, 2, BSZ);
    k_att<<<g3, 256, SMEM_ATT>>>();
    dim3 g4(8, BSZ);
    k_out<<<g4, 256>>>(out);
}